// round 12
// baseline (speedup 1.0000x reference)
#include <cuda_runtime.h>
#include <math.h>
#include <stdint.h>

#define B_    2048
#define S_    100
#define POS_  2
#define E_    256
#define H_    256
#define G4_   1024
#define BS_   (B_*S_)

__device__ float g_emb[(size_t)S_*B_*E_];
__device__ float g_encgx[(size_t)S_*B_*G4_];   // permuted gate layout
__device__ float g_encout[(size_t)S_*B_*H_];
__device__ float g_kptr[(size_t)S_*B_*H_];
__device__ float g_kgl[(size_t)S_*B_*H_];
__device__ float g_hbuf[2][B_*H_];
__device__ float g_c[B_*H_];
__device__ float g_query[B_*H_];
__device__ unsigned char g_mask[B_*S_];
__device__ float g_decin[B_*E_];
__device__ unsigned g_keys[2*S_];
__device__ float g_eWih_p[G4_*E_];
__device__ float g_eWhh_p[G4_*H_];
__device__ float g_dWih_p[G4_*E_];
__device__ float g_dWhh_p[G4_*H_];
__device__ float g_ebih_p[G4_], g_ebhh_p[G4_], g_dbih_p[G4_], g_dbhh_p[G4_];
__device__ float g_gWqT[H_*H_];   // [k][n]
__device__ float g_pWqT[H_*H_];
__device__ unsigned g_cnt = 0;
__device__ unsigned g_gen = 0;

__device__ __forceinline__ void gsync() {
    __syncthreads();
    if (threadIdx.x == 0) {
        __threadfence();
        unsigned gen = *(volatile unsigned*)&g_gen;
        if (atomicAdd(&g_cnt, 1u) == gridDim.x - 1) {
            g_cnt = 0;
            __threadfence();
            *(volatile unsigned*)&g_gen = gen + 1u;
        } else {
            while (*(volatile unsigned*)&g_gen == gen) { __nanosleep(64); }
            __threadfence();
        }
    }
    __syncthreads();
}

// ---------------- packed f32x2 ----------------
__device__ __forceinline__ unsigned long long pk2(float lo, float hi) {
    unsigned long long r; asm("mov.b64 %0,{%1,%2};" : "=l"(r) : "f"(lo), "f"(hi)); return r;
}
__device__ __forceinline__ void upk2(unsigned long long v, float &lo, float &hi) {
    asm("mov.b64 {%0,%1},%2;" : "=f"(lo), "=f"(hi) : "l"(v));
}
__device__ __forceinline__ unsigned long long mul2(unsigned long long a, unsigned long long b) {
    unsigned long long d; asm("mul.rn.f32x2 %0,%1,%2;" : "=l"(d) : "l"(a), "l"(b)); return d;
}
__device__ __forceinline__ unsigned long long add2(unsigned long long a, unsigned long long b) {
    unsigned long long d; asm("add.rn.f32x2 %0,%1,%2;" : "=l"(d) : "l"(a), "l"(b)); return d;
}
__device__ __forceinline__ unsigned long long fma2_(unsigned long long a, unsigned long long b,
                                                    unsigned long long c) {
    unsigned long long d; asm("fma.rn.f32x2 %0,%1,%2,%3;" : "=l"(d) : "l"(a), "l"(b), "l"(c)); return d;
}

__device__ __forceinline__ float xla_tanh(float x) {
    const float CL = 7.90531110763549805f;
    float xc = fminf(fmaxf(x, -CL), CL);
    float x2 = __fmul_rn(xc, xc);
    float p = -2.76076847742355e-16f;
    p = __fadd_rn(__fmul_rn(x2, p),  2.00018790482477e-13f);
    p = __fadd_rn(__fmul_rn(x2, p), -8.60467152213735e-11f);
    p = __fadd_rn(__fmul_rn(x2, p),  5.12229709037114e-08f);
    p = __fadd_rn(__fmul_rn(x2, p),  1.48572235717979e-05f);
    p = __fadd_rn(__fmul_rn(x2, p),  6.37261928875436e-04f);
    p = __fadd_rn(__fmul_rn(x2, p),  4.89352455891786e-03f);
    float num = __fmul_rn(xc, p);
    float q = 1.19825839466702e-06f;
    q = __fadd_rn(__fmul_rn(x2, q),  1.18534705686654e-04f);
    q = __fadd_rn(__fmul_rn(x2, q),  2.26843463243900e-03f);
    q = __fadd_rn(__fmul_rn(x2, q),  4.89352518554385e-03f);
    float r = __fdiv_rn(num, q);
    return fabsf(x) < 0.0004f ? x : r;
}
__device__ __forceinline__ float xla_sigmoid(float x) {
    return __fdiv_rn(1.0f, __fadd_rn(1.0f, expf(-x)));
}

struct T2C { unsigned long long c[11]; };
__device__ __forceinline__ T2C make_t2c() {
    T2C t;
    t.c[0]  = pk2(-2.76076847742355e-16f, -2.76076847742355e-16f);
    t.c[1]  = pk2( 2.00018790482477e-13f,  2.00018790482477e-13f);
    t.c[2]  = pk2(-8.60467152213735e-11f, -8.60467152213735e-11f);
    t.c[3]  = pk2( 5.12229709037114e-08f,  5.12229709037114e-08f);
    t.c[4]  = pk2( 1.48572235717979e-05f,  1.48572235717979e-05f);
    t.c[5]  = pk2( 6.37261928875436e-04f,  6.37261928875436e-04f);
    t.c[6]  = pk2( 4.89352455891786e-03f,  4.89352455891786e-03f);
    t.c[7]  = pk2( 1.19825839466702e-06f,  1.19825839466702e-06f);
    t.c[8]  = pk2( 1.18534705686654e-04f,  1.18534705686654e-04f);
    t.c[9]  = pk2( 2.26843463243900e-03f,  2.26843463243900e-03f);
    t.c[10] = pk2( 4.89352518554385e-03f,  4.89352518554385e-03f);
    return t;
}
__device__ __forceinline__ void tanh2(const T2C &K, float a, float b, float &ra, float &rb) {
    const float CL = 7.90531110763549805f;
    float ca = fminf(fmaxf(a, -CL), CL);
    float cb = fminf(fmaxf(b, -CL), CL);
    unsigned long long X  = pk2(ca, cb);
    unsigned long long X2 = mul2(X, X);
    unsigned long long P  = K.c[0];
    P = add2(mul2(X2, P), K.c[1]);
    P = add2(mul2(X2, P), K.c[2]);
    P = add2(mul2(X2, P), K.c[3]);
    P = add2(mul2(X2, P), K.c[4]);
    P = add2(mul2(X2, P), K.c[5]);
    P = add2(mul2(X2, P), K.c[6]);
    unsigned long long NUM = mul2(X, P);
    unsigned long long Q = K.c[7];
    Q = add2(mul2(X2, Q), K.c[8]);
    Q = add2(mul2(X2, Q), K.c[9]);
    Q = add2(mul2(X2, Q), K.c[10]);
    float na, nb, qa, qb;
    upk2(NUM, na, nb);
    upk2(Q, qa, qb);
    float da = __fdiv_rn(na, qa);
    float db = __fdiv_rn(nb, qb);
    ra = fabsf(a) < 0.0004f ? a : da;
    rb = fabsf(b) < 0.0004f ? b : db;
}

__device__ __forceinline__ unsigned rotl32(unsigned x, int d) {
    return (x << d) | (x >> (32 - d));
}
__device__ __forceinline__ void threefry(unsigned ks0, unsigned ks1,
                                         unsigned &x0, unsigned &x1) {
    unsigned ks2 = ks0 ^ ks1 ^ 0x1BD11BDAu;
    x0 += ks0; x1 += ks1;
#define TF_R(r) { x0 += x1; x1 = rotl32(x1, r); x1 ^= x0; }
    TF_R(13) TF_R(15) TF_R(26) TF_R(6)  x0 += ks1; x1 += ks2 + 1u;
    TF_R(17) TF_R(29) TF_R(16) TF_R(24) x0 += ks2; x1 += ks0 + 2u;
    TF_R(13) TF_R(15) TF_R(26) TF_R(6)  x0 += ks0; x1 += ks1 + 3u;
    TF_R(17) TF_R(29) TF_R(16) TF_R(24) x0 += ks1; x1 += ks2 + 4u;
    TF_R(13) TF_R(15) TF_R(26) TF_R(6)  x0 += ks2; x1 += ks0 + 5u;
#undef TF_R
}
__device__ __forceinline__ float gumbel_at(unsigned k0, unsigned k1, unsigned i) {
    unsigned x0 = 0u, x1 = i;
    threefry(k0, k1, x0, x1);
    unsigned bits = x0 ^ x1;
    float f = __fadd_rn(__uint_as_float((bits >> 9) | 0x3f800000u), -1.0f);
    const float TINY = 1.17549435e-38f;
    float u = fmaxf(TINY, __fadd_rn(__fmul_rn(f, 1.0f - TINY), TINY));
    return -logf(-logf(u));
}

struct AttnSh {
    float hs[H_];
    float sq[H_];
    float su[112];
    float ws[112];
    float red[4];
    int   chosen;
    unsigned char smask[112];
};
union ShU {
    float gemm[2*16*68];
    AttnSh attn;
};

// ---------------- fused gemm ----------------
template<int EPI>
__device__ void dev_gemm_f(const float* __restrict__ A, const float* __restrict__ W, int K,
                           const float* __restrict__ A2, const float* __restrict__ W2, int K2,
                           float* __restrict__ C, int M, int N,
                           const float* __restrict__ bias,
                           const float* __restrict__ gx,
                           const float* __restrict__ bih, const float* __restrict__ bhh,
                           float* __restrict__ cst, float* __restrict__ hout,
                           float* __restrict__ encout,
                           float* smem) {
    float (*As)[68] = (float(*)[68])smem;
    float (*Bs)[68] = (float(*)[68])(smem + 16*68);
    const int tid = threadIdx.x;
    const int tx = tid & 15, ty = tid >> 4;
    const int lm = tid >> 2, lk = (tid & 3) << 2;
    const int tilesN = N >> 6;
    const int tiles = (M >> 6) * tilesN;
    const int nc1 = K >> 4;
    const int nc2 = A2 ? (K2 >> 4) : 0;
    const int nc = nc1 + nc2;
    for (int tI = blockIdx.x; tI < tiles; tI += gridDim.x) {
        const int row0 = (tI / tilesN) << 6;
        const int col0 = (tI % tilesN) << 6;
        unsigned long long acc[4][2];
#pragma unroll
        for (int i = 0; i < 4; i++) { acc[i][0] = 0ull; acc[i][1] = 0ull; }
        const float* ArowA = A + (size_t)(row0 + lm) * K + lk;
        const float* WrowA = W + (size_t)(col0 + lm) * K + lk;
        const float* ArowB = A2 ? A2 + (size_t)(row0 + lm) * K2 + lk : nullptr;
        const float* WrowB = A2 ? W2 + (size_t)(col0 + lm) * K2 + lk : nullptr;
        float4 a4 = *(const float4*)ArowA;
        float4 b4 = *(const float4*)WrowA;
        for (int c = 0; c < nc; c++) {
            As[lk+0][lm]=a4.x; As[lk+1][lm]=a4.y; As[lk+2][lm]=a4.z; As[lk+3][lm]=a4.w;
            Bs[lk+0][lm]=b4.x; Bs[lk+1][lm]=b4.y; Bs[lk+2][lm]=b4.z; Bs[lk+3][lm]=b4.w;
            __syncthreads();
            if (c + 1 < nc) {
                int cn = c + 1;
                if (cn < nc1) {
                    a4 = *(const float4*)(ArowA + cn*16);
                    b4 = *(const float4*)(WrowA + cn*16);
                } else {
                    int cc = cn - nc1;
                    a4 = *(const float4*)(ArowB + cc*16);
                    b4 = *(const float4*)(WrowB + cc*16);
                }
            }
#pragma unroll
            for (int kk = 0; kk < 16; kk++) {
                float4 av = *(const float4*)&As[kk][ty << 2];
                ulonglong2 bq = *(const ulonglong2*)&Bs[kk][tx << 2];
                float am[4] = {av.x, av.y, av.z, av.w};
#pragma unroll
                for (int i = 0; i < 4; i++) {
                    unsigned long long amp = pk2(am[i], am[i]);
                    acc[i][0] = fma2_(amp, bq.x, acc[i][0]);
                    acc[i][1] = fma2_(amp, bq.y, acc[i][1]);
                }
            }
            __syncthreads();
        }
        if (EPI == 0) {
#pragma unroll
            for (int i = 0; i < 4; i++) {
                int m = row0 + (ty << 2) + i;
                float c0, c1, c2, c3;
                upk2(acc[i][0], c0, c1);
                upk2(acc[i][1], c2, c3);
                float vv[4] = {c0, c1, c2, c3};
#pragma unroll
                for (int j = 0; j < 4; j++) {
                    int n = col0 + (tx << 2) + j;
                    float v = vv[j];
                    if (bias) v = __fadd_rn(v, bias[n]);
                    C[(size_t)m * N + n] = v;
                }
            }
        } else {
            const int jq = (col0 >> 2) + tx;
            float4 bh4 = *(const float4*)&bhh[col0 + (tx << 2)];
            float4 bi4;
            if (EPI == 2) bi4 = *(const float4*)&bih[col0 + (tx << 2)];
#pragma unroll
            for (int i = 0; i < 4; i++) {
                int m = row0 + (ty << 2) + i;
                float c0, c1, c2, c3;
                upk2(acc[i][0], c0, c1);
                upk2(acc[i][1], c2, c3);
                float gi, gf, gg, go;
                if (EPI == 1) {
                    float4 gx4 = *(const float4*)&gx[(size_t)m*G4_ + col0 + (tx << 2)];
                    gi = __fadd_rn(__fadd_rn(gx4.x, c0), bh4.x);
                    gf = __fadd_rn(__fadd_rn(gx4.y, c1), bh4.y);
                    gg = __fadd_rn(__fadd_rn(gx4.z, c2), bh4.z);
                    go = __fadd_rn(__fadd_rn(gx4.w, c3), bh4.w);
                } else {
                    gi = __fadd_rn(__fadd_rn(c0, bi4.x), bh4.x);
                    gf = __fadd_rn(__fadd_rn(c1, bi4.y), bh4.y);
                    gg = __fadd_rn(__fadd_rn(c2, bi4.z), bh4.z);
                    go = __fadd_rn(__fadd_rn(c3, bi4.w), bh4.w);
                }
                float iv = xla_sigmoid(gi);
                float fv = xla_sigmoid(gf);
                float gv = xla_tanh(gg);
                float ov = xla_sigmoid(go);
                size_t ci = (size_t)m * H_ + jq;
                float cn = __fadd_rn(__fmul_rn(fv, cst[ci]), __fmul_rn(iv, gv));
                float hn = __fmul_rn(ov, xla_tanh(cn));
                cst[ci] = cn;
                hout[ci] = hn;
                if (encout) encout[ci] = hn;
            }
        }
    }
}

// attention with fused q projection. MODE 0: glimpse (two-pass global k).
// MODE 1: pointer + sampling.
template<int MODE>
__device__ void dev_attn(const float* __restrict__ hsrc, const float* __restrict__ WqT,
                         const float* __restrict__ qb,
                         const float* __restrict__ k,
                         const float* __restrict__ V, unsigned char* __restrict__ mask,
                         float* __restrict__ outq,
                         const unsigned* __restrict__ keys, const float* __restrict__ emb,
                         float* __restrict__ decin, float* __restrict__ out, int t,
                         AttnSh* A) {
    const int tid = threadIdx.x;
    const int warp = tid >> 5, lane = tid & 31;
    const T2C K2 = make_t2c();
    float4 v0q = *(const float4*)&V[lane << 3];
    float4 v1q = *(const float4*)&V[(lane << 3) + 4];
    float qbv = qb[tid];

    for (int b = blockIdx.x; b < B_; b += gridDim.x) {
        if (tid < S_) A->smask[tid] = mask[(size_t)b*S_ + tid];
        A->hs[tid] = hsrc[(size_t)b*H_ + tid];
        __syncthreads();
        // fused q projection: q[tid] = sum_k hs[k]*WqT[k][tid]  (k ascending) + bias
        {
            float acc = 0.f;
            const float* wp = WqT + tid;
#pragma unroll 8
            for (int kk = 0; kk < H_; kk++)
                acc = fmaf(A->hs[kk], wp[kk << 8], acc);
            A->sq[tid] = __fadd_rn(acc, qbv);
        }
        __syncthreads();
        float4 q0q = *(const float4*)&A->sq[lane << 3];
        float4 q1q = *(const float4*)&A->sq[(lane << 3) + 4];

        for (int s = warp; s < S_; s += 8) {
            float x[8], tz[8];
            const float* krow = k + ((size_t)s*B_ + b)*H_ + (lane << 3);
            float4 k0v = *(const float4*)krow;
            float4 k1v = *(const float4*)(krow + 4);
            x[0] = __fadd_rn(q0q.x, k0v.x); x[1] = __fadd_rn(q0q.y, k0v.y);
            x[2] = __fadd_rn(q0q.z, k0v.z); x[3] = __fadd_rn(q0q.w, k0v.w);
            x[4] = __fadd_rn(q1q.x, k1v.x); x[5] = __fadd_rn(q1q.y, k1v.y);
            x[6] = __fadd_rn(q1q.z, k1v.z); x[7] = __fadd_rn(q1q.w, k1v.w);
            tanh2(K2, x[0], x[1], tz[0], tz[1]);
            tanh2(K2, x[2], x[3], tz[2], tz[3]);
            tanh2(K2, x[4], x[5], tz[4], tz[5]);
            tanh2(K2, x[6], x[7], tz[6], tz[7]);
            float p = 0.f;
            p = fmaf(tz[0], v0q.x, p); p = fmaf(tz[1], v0q.y, p);
            p = fmaf(tz[2], v0q.z, p); p = fmaf(tz[3], v0q.w, p);
            p = fmaf(tz[4], v1q.x, p); p = fmaf(tz[5], v1q.y, p);
            p = fmaf(tz[6], v1q.z, p); p = fmaf(tz[7], v1q.w, p);
#pragma unroll
            for (int off = 16; off > 0; off >>= 1) p += __shfl_xor_sync(0xffffffffu, p, off);
            if (lane == 0) {
                float lg = __fmul_rn(10.0f, xla_tanh(p));
                A->su[s] = A->smask[s] ? -INFINITY : lg;
            }
        }
        __syncthreads();

        if (MODE == 0) {
            if (warp == 0) {
                float m = -INFINITY;
#pragma unroll
                for (int r = 0; r < 4; r++) { int s = lane + (r<<5); if (s < S_) m = fmaxf(m, A->su[s]); }
#pragma unroll
                for (int off = 16; off > 0; off >>= 1) m = fmaxf(m, __shfl_xor_sync(0xffffffffu, m, off));
                float sum = 0.f;
#pragma unroll
                for (int r = 0; r < 4; r++) { int s = lane + (r<<5); if (s < S_) sum += expf(__fadd_rn(A->su[s], -m)); }
#pragma unroll
                for (int off = 16; off > 0; off >>= 1) sum += __shfl_xor_sync(0xffffffffu, sum, off);
                if (lane == 0) { A->red[0] = m; A->red[1] = sum; }
            }
            __syncthreads();
            if (tid < S_) A->ws[tid] = __fdiv_rn(expf(__fadd_rn(A->su[tid], -A->red[0])), A->red[1]);
            __syncthreads();
            float acc = 0.f;
            for (int s = 0; s < S_; s++)
                acc = fmaf(A->ws[s], k[((size_t)s*B_ + b)*H_ + tid], acc);
            outq[(size_t)b*H_ + tid] = acc;
            __syncthreads();
        } else {
            const unsigned k0 = keys[2*t], k1 = keys[2*t+1];
            if (warp == 0) {
                float best = -INFINITY; int bi = S_; float mx = -INFINITY;
#pragma unroll
                for (int r = 0; r < 4; r++) {
                    int s = lane + (r << 5);
                    if (s < S_) {
                        float lv = A->su[s];
                        mx = fmaxf(mx, lv);
                        float z = __fadd_rn(lv, gumbel_at(k0, k1, (unsigned)(b*S_ + s)));
                        if (z > best) { best = z; bi = s; }
                    }
                }
#pragma unroll
                for (int off = 16; off > 0; off >>= 1) {
                    float oz = __shfl_xor_sync(0xffffffffu, best, off);
                    int   oi = __shfl_xor_sync(0xffffffffu, bi,   off);
                    if (oz > best || (oz == best && oi < bi)) { best = oz; bi = oi; }
                    mx = fmaxf(mx, __shfl_xor_sync(0xffffffffu, mx, off));
                }
                float se = 0.f;
#pragma unroll
                for (int r = 0; r < 4; r++) { int s = lane + (r<<5); if (s < S_) se += expf(__fadd_rn(A->su[s], -mx)); }
#pragma unroll
                for (int off = 16; off > 0; off >>= 1) se += __shfl_xor_sync(0xffffffffu, se, off);
                if (lane == 0) {
                    A->chosen = bi;
                    out[(size_t)b*S_ + t] = __fadd_rn(__fadd_rn(A->su[bi], -mx), -logf(se));
                    out[(size_t)BS_ + (size_t)b*S_ + t] = (float)bi;
                    mask[(size_t)b*S_ + bi] = 1;
                }
            }
            __syncthreads();
            int ch = A->chosen;
            decin[(size_t)b*E_ + tid] = emb[((size_t)ch*B_ + b)*E_ + tid];
            __syncthreads();
        }
    }
}

__global__ __launch_bounds__(256, 3)
void mega_kernel(const float* __restrict__ inp,
                 const float* __restrict__ embW, const float* __restrict__ embB,
                 const float* __restrict__ eWih, const float* __restrict__ eWhh,
                 const float* __restrict__ ebih, const float* __restrict__ ebhh,
                 const float* __restrict__ dWih, const float* __restrict__ dWhh,
                 const float* __restrict__ dbih, const float* __restrict__ dbhh,
                 const float* __restrict__ pWq,  const float* __restrict__ pbq,
                 const float* __restrict__ pWk,  const float* __restrict__ pbk,
                 const float* __restrict__ pV,
                 const float* __restrict__ gWq,  const float* __restrict__ gbq,
                 const float* __restrict__ gWk,  const float* __restrict__ gbk,
                 const float* __restrict__ gV,
                 const float* __restrict__ sos,
                 float* __restrict__ out) {
    __shared__ ShU sh;
    const int tid = threadIdx.x;
    const int gstride = gridDim.x * blockDim.x;
    const int gidx = blockIdx.x * blockDim.x + tid;

    // phase 0: init, weight permutes/transposes, keys, embedding
    for (int i = gidx; i < B_*H_; i += gstride) { g_hbuf[0][i] = 0.f; g_c[i] = 0.f; }
    for (int i = gidx; i < B_*E_; i += gstride) g_decin[i] = sos[i & (E_-1)];
    for (int i = gidx; i < B_*S_; i += gstride) g_mask[i] = 0;
    for (int idx = gidx; idx < G4_*E_; idx += gstride) {
        int row = idx >> 8, kk = idx & 255;
        int j = row >> 2, g = row & 3;
        int old = (g*H_ + j)*E_ + kk;
        g_eWih_p[idx] = eWih[old];
        g_eWhh_p[idx] = eWhh[old];
        g_dWih_p[idx] = dWih[old];
        g_dWhh_p[idx] = dWhh[old];
    }
    for (int idx = gidx; idx < H_*H_; idx += gstride) {
        int kk = idx >> 8, n = idx & 255;
        g_gWqT[idx] = gWq[n*H_ + kk];
        g_pWqT[idx] = pWq[n*H_ + kk];
    }
    for (int idx = gidx; idx < G4_; idx += gstride) {
        int j = idx >> 2, g = idx & 3;
        int old = g*H_ + j;
        g_ebih_p[idx] = ebih[old];
        g_ebhh_p[idx] = ebhh[old];
        g_dbih_p[idx] = dbih[old];
        g_dbhh_p[idx] = dbhh[old];
    }
    if (blockIdx.x == 0 && tid < S_) {
        unsigned x0 = 0u, x1 = (unsigned)tid;
        threefry(0u, 42u, x0, x1);
        g_keys[2*tid]   = x0;
        g_keys[2*tid+1] = x1;
    }
    for (int idx = gidx; idx < S_*B_*E_; idx += gstride) {
        int e = idx & (E_-1);
        int i = idx >> 8;
        int s = i >> 11;
        int b = i & (B_-1);
        float x0 = inp[((size_t)b*S_ + s)*POS_ + 0];
        float x1 = inp[((size_t)b*S_ + s)*POS_ + 1];
        float dotv = fmaf(x1, embW[e*POS_ + 1], __fmul_rn(x0, embW[e*POS_ + 0]));
        g_emb[idx] = __fadd_rn(dotv, embB[e]);
    }
    gsync();

    dev_gemm_f<0>(g_emb, g_eWih_p, E_, nullptr, nullptr, 0, g_encgx, BS_, G4_,
                  g_ebih_p, nullptr, nullptr, nullptr, nullptr, nullptr, nullptr, sh.gemm);
    gsync();

    for (int t = 0; t < S_; t++) {
        dev_gemm_f<1>(g_hbuf[t & 1], g_eWhh_p, H_, nullptr, nullptr, 0,
                      nullptr, B_, G4_, nullptr,
                      g_encgx + (size_t)t*B_*G4_, nullptr, g_ebhh_p,
                      g_c, g_hbuf[(t + 1) & 1], g_encout + (size_t)t*B_*H_, sh.gemm);
        gsync();
    }

    dev_gemm_f<0>(g_encout, pWk, H_, nullptr, nullptr, 0, g_kptr, BS_, H_,
                  pbk, nullptr, nullptr, nullptr, nullptr, nullptr, nullptr, sh.gemm);
    dev_gemm_f<0>(g_encout, gWk, H_, nullptr, nullptr, 0, g_kgl, BS_, H_,
                  gbk, nullptr, nullptr, nullptr, nullptr, nullptr, nullptr, sh.gemm);
    gsync();

    for (int t = 0; t < S_; t++) {
        dev_gemm_f<2>(g_decin, g_dWih_p, E_, g_hbuf[t & 1], g_dWhh_p, H_,
                      nullptr, B_, G4_, nullptr,
                      nullptr, g_dbih_p, g_dbhh_p,
                      g_c, g_hbuf[(t + 1) & 1], nullptr, sh.gemm);
        gsync();
        float* hcur = g_hbuf[(t + 1) & 1];
        dev_attn<0>(hcur, g_gWqT, gbq, g_kgl, gV, g_mask, g_query,
                    nullptr, nullptr, nullptr, nullptr, t, &sh.attn);
        gsync();
        dev_attn<1>(g_query, g_pWqT, pbq, g_kptr, pV, g_mask, nullptr,
                    g_keys, g_emb, g_decin, out, t, &sh.attn);
        gsync();
    }
}

extern "C" void kernel_launch(void* const* d_in, const int* in_sizes, int n_in,
                              void* d_out, int out_size) {
    const float* inp  = (const float*)d_in[0];
    const float* embW = (const float*)d_in[1];
    const float* embB = (const float*)d_in[2];
    const float* eWih = (const float*)d_in[3];
    const float* eWhh = (const float*)d_in[4];
    const float* ebih = (const float*)d_in[5];
    const float* ebhh = (const float*)d_in[6];
    const float* dWih = (const float*)d_in[7];
    const float* dWhh = (const float*)d_in[8];
    const float* dbih = (const float*)d_in[9];
    const float* dbhh = (const float*)d_in[10];
    const float* pWq  = (const float*)d_in[11];
    const float* pbq  = (const float*)d_in[12];
    const float* pWk  = (const float*)d_in[13];
    const float* pbk  = (const float*)d_in[14];
    const float* pV   = (const float*)d_in[15];
    const float* gWq  = (const float*)d_in[16];
    const float* gbq  = (const float*)d_in[17];
    const float* gWk  = (const float*)d_in[18];
    const float* gbk  = (const float*)d_in[19];
    const float* gV   = (const float*)d_in[20];
    const float* sos  = (const float*)d_in[21];
    float* out = (float*)d_out;

    int sms = 0;
    cudaDeviceGetAttribute(&sms, cudaDevAttrMultiProcessorCount, 0);
    int nblk = sms * 3;

    mega_kernel<<<nblk, 256>>>(
        inp, embW, embB, eWih, eWhh, ebih, ebhh,
        dWih, dWhh, dbih, dbhh,
        pWq, pbq, pWk, pbk, pV,
        gWq, gbq, gWk, gbk, gV, sos, out);
}

// round 13
// speedup vs baseline: 1.1152x; 1.1152x over previous
#include <cuda_runtime.h>
#include <math.h>
#include <stdint.h>

#define B_    2048
#define S_    100
#define POS_  2
#define E_    256
#define H_    256
#define G4_   1024
#define BS_   (B_*S_)

__device__ float g_emb[(size_t)S_*B_*E_];
__device__ float g_encgx[(size_t)S_*B_*G4_];   // permuted gate layout
__device__ float g_encout[(size_t)S_*B_*H_];
__device__ float g_kptr[(size_t)S_*B_*H_];
__device__ float g_kgl[(size_t)S_*B_*H_];
__device__ float g_hbuf[2][B_*H_];
__device__ float g_c[B_*H_];
__device__ unsigned char g_mask[B_*S_];
__device__ float g_decin[B_*E_];
__device__ unsigned g_keys[2*S_];
__device__ float g_eWih_p[G4_*E_];
__device__ float g_eWhh_p[G4_*H_];
__device__ float g_dWih_p[G4_*E_];
__device__ float g_dWhh_p[G4_*H_];
__device__ float g_ebih_p[G4_], g_ebhh_p[G4_], g_dbih_p[G4_], g_dbhh_p[G4_];
__device__ float g_gWqT[H_*H_];   // [k][n]
__device__ float g_pWqT[H_*H_];
__device__ unsigned g_cnt = 0;
__device__ unsigned g_gen = 0;

__device__ __forceinline__ void gsync() {
    __syncthreads();
    if (threadIdx.x == 0) {
        __threadfence();
        unsigned gen = *(volatile unsigned*)&g_gen;
        if (atomicAdd(&g_cnt, 1u) == gridDim.x - 1) {
            g_cnt = 0;
            __threadfence();
            *(volatile unsigned*)&g_gen = gen + 1u;
        } else {
            while (*(volatile unsigned*)&g_gen == gen) { __nanosleep(64); }
            __threadfence();
        }
    }
    __syncthreads();
}

// ---------------- packed f32x2 ----------------
__device__ __forceinline__ unsigned long long pk2(float lo, float hi) {
    unsigned long long r; asm("mov.b64 %0,{%1,%2};" : "=l"(r) : "f"(lo), "f"(hi)); return r;
}
__device__ __forceinline__ void upk2(unsigned long long v, float &lo, float &hi) {
    asm("mov.b64 {%0,%1},%2;" : "=f"(lo), "=f"(hi) : "l"(v));
}
__device__ __forceinline__ unsigned long long mul2(unsigned long long a, unsigned long long b) {
    unsigned long long d; asm("mul.rn.f32x2 %0,%1,%2;" : "=l"(d) : "l"(a), "l"(b)); return d;
}
__device__ __forceinline__ unsigned long long add2(unsigned long long a, unsigned long long b) {
    unsigned long long d; asm("add.rn.f32x2 %0,%1,%2;" : "=l"(d) : "l"(a), "l"(b)); return d;
}
__device__ __forceinline__ unsigned long long fma2_(unsigned long long a, unsigned long long b,
                                                    unsigned long long c) {
    unsigned long long d; asm("fma.rn.f32x2 %0,%1,%2,%3;" : "=l"(d) : "l"(a), "l"(b), "l"(c)); return d;
}

__device__ __forceinline__ float xla_tanh(float x) {
    const float CL = 7.90531110763549805f;
    float xc = fminf(fmaxf(x, -CL), CL);
    float x2 = __fmul_rn(xc, xc);
    float p = -2.76076847742355e-16f;
    p = __fadd_rn(__fmul_rn(x2, p),  2.00018790482477e-13f);
    p = __fadd_rn(__fmul_rn(x2, p), -8.60467152213735e-11f);
    p = __fadd_rn(__fmul_rn(x2, p),  5.12229709037114e-08f);
    p = __fadd_rn(__fmul_rn(x2, p),  1.48572235717979e-05f);
    p = __fadd_rn(__fmul_rn(x2, p),  6.37261928875436e-04f);
    p = __fadd_rn(__fmul_rn(x2, p),  4.89352455891786e-03f);
    float num = __fmul_rn(xc, p);
    float q = 1.19825839466702e-06f;
    q = __fadd_rn(__fmul_rn(x2, q),  1.18534705686654e-04f);
    q = __fadd_rn(__fmul_rn(x2, q),  2.26843463243900e-03f);
    q = __fadd_rn(__fmul_rn(x2, q),  4.89352518554385e-03f);
    float r = __fdiv_rn(num, q);
    return fabsf(x) < 0.0004f ? x : r;
}
__device__ __forceinline__ float xla_sigmoid(float x) {
    return __fdiv_rn(1.0f, __fadd_rn(1.0f, expf(-x)));
}

struct T2C { unsigned long long c[11]; };
__device__ __forceinline__ T2C make_t2c() {
    T2C t;
    t.c[0]  = pk2(-2.76076847742355e-16f, -2.76076847742355e-16f);
    t.c[1]  = pk2( 2.00018790482477e-13f,  2.00018790482477e-13f);
    t.c[2]  = pk2(-8.60467152213735e-11f, -8.60467152213735e-11f);
    t.c[3]  = pk2( 5.12229709037114e-08f,  5.12229709037114e-08f);
    t.c[4]  = pk2( 1.48572235717979e-05f,  1.48572235717979e-05f);
    t.c[5]  = pk2( 6.37261928875436e-04f,  6.37261928875436e-04f);
    t.c[6]  = pk2( 4.89352455891786e-03f,  4.89352455891786e-03f);
    t.c[7]  = pk2( 1.19825839466702e-06f,  1.19825839466702e-06f);
    t.c[8]  = pk2( 1.18534705686654e-04f,  1.18534705686654e-04f);
    t.c[9]  = pk2( 2.26843463243900e-03f,  2.26843463243900e-03f);
    t.c[10] = pk2( 4.89352518554385e-03f,  4.89352518554385e-03f);
    return t;
}
__device__ __forceinline__ void tanh2(const T2C &K, float a, float b, float &ra, float &rb) {
    const float CL = 7.90531110763549805f;
    float ca = fminf(fmaxf(a, -CL), CL);
    float cb = fminf(fmaxf(b, -CL), CL);
    unsigned long long X  = pk2(ca, cb);
    unsigned long long X2 = mul2(X, X);
    unsigned long long P  = K.c[0];
    P = add2(mul2(X2, P), K.c[1]);
    P = add2(mul2(X2, P), K.c[2]);
    P = add2(mul2(X2, P), K.c[3]);
    P = add2(mul2(X2, P), K.c[4]);
    P = add2(mul2(X2, P), K.c[5]);
    P = add2(mul2(X2, P), K.c[6]);
    unsigned long long NUM = mul2(X, P);
    unsigned long long Q = K.c[7];
    Q = add2(mul2(X2, Q), K.c[8]);
    Q = add2(mul2(X2, Q), K.c[9]);
    Q = add2(mul2(X2, Q), K.c[10]);
    float na, nb, qa, qb;
    upk2(NUM, na, nb);
    upk2(Q, qa, qb);
    float da = __fdiv_rn(na, qa);
    float db = __fdiv_rn(nb, qb);
    ra = fabsf(a) < 0.0004f ? a : da;
    rb = fabsf(b) < 0.0004f ? b : db;
}

__device__ __forceinline__ unsigned rotl32(unsigned x, int d) {
    return (x << d) | (x >> (32 - d));
}
__device__ __forceinline__ void threefry(unsigned ks0, unsigned ks1,
                                         unsigned &x0, unsigned &x1) {
    unsigned ks2 = ks0 ^ ks1 ^ 0x1BD11BDAu;
    x0 += ks0; x1 += ks1;
#define TF_R(r) { x0 += x1; x1 = rotl32(x1, r); x1 ^= x0; }
    TF_R(13) TF_R(15) TF_R(26) TF_R(6)  x0 += ks1; x1 += ks2 + 1u;
    TF_R(17) TF_R(29) TF_R(16) TF_R(24) x0 += ks2; x1 += ks0 + 2u;
    TF_R(13) TF_R(15) TF_R(26) TF_R(6)  x0 += ks0; x1 += ks1 + 3u;
    TF_R(17) TF_R(29) TF_R(16) TF_R(24) x0 += ks1; x1 += ks2 + 4u;
    TF_R(13) TF_R(15) TF_R(26) TF_R(6)  x0 += ks2; x1 += ks0 + 5u;
#undef TF_R
}
__device__ __forceinline__ float gumbel_at(unsigned k0, unsigned k1, unsigned i) {
    unsigned x0 = 0u, x1 = i;
    threefry(k0, k1, x0, x1);
    unsigned bits = x0 ^ x1;
    float f = __fadd_rn(__uint_as_float((bits >> 9) | 0x3f800000u), -1.0f);
    const float TINY = 1.17549435e-38f;
    float u = fmaxf(TINY, __fadd_rn(__fmul_rn(f, 1.0f - TINY), TINY));
    return -logf(-logf(u));
}

struct AttnSh {
    float hs[H_];
    float sq[H_];
    float su[112];
    float ws[112];
    float red[4];
    int   chosen;
    unsigned char smask[112];
};
union ShU {
    float gemm[2*16*68];
    AttnSh attn;
};

// ---------------- fused gemm ----------------
template<int EPI>
__device__ void dev_gemm_f(const float* __restrict__ A, const float* __restrict__ W, int K,
                           const float* __restrict__ A2, const float* __restrict__ W2, int K2,
                           float* __restrict__ C, int M, int N,
                           const float* __restrict__ bias,
                           const float* __restrict__ gx,
                           const float* __restrict__ bih, const float* __restrict__ bhh,
                           float* __restrict__ cst, float* __restrict__ hout,
                           float* __restrict__ encout,
                           float* smem) {
    float (*As)[68] = (float(*)[68])smem;
    float (*Bs)[68] = (float(*)[68])(smem + 16*68);
    const int tid = threadIdx.x;
    const int tx = tid & 15, ty = tid >> 4;
    const int lm = tid >> 2, lk = (tid & 3) << 2;
    const int tilesN = N >> 6;
    const int tiles = (M >> 6) * tilesN;
    const int nc1 = K >> 4;
    const int nc2 = A2 ? (K2 >> 4) : 0;
    const int nc = nc1 + nc2;
    for (int tI = blockIdx.x; tI < tiles; tI += gridDim.x) {
        const int row0 = (tI / tilesN) << 6;
        const int col0 = (tI % tilesN) << 6;
        unsigned long long acc[4][2];
#pragma unroll
        for (int i = 0; i < 4; i++) { acc[i][0] = 0ull; acc[i][1] = 0ull; }
        const float* ArowA = A + (size_t)(row0 + lm) * K + lk;
        const float* WrowA = W + (size_t)(col0 + lm) * K + lk;
        const float* ArowB = A2 ? A2 + (size_t)(row0 + lm) * K2 + lk : nullptr;
        const float* WrowB = A2 ? W2 + (size_t)(col0 + lm) * K2 + lk : nullptr;
        float4 a4 = *(const float4*)ArowA;
        float4 b4 = *(const float4*)WrowA;
        for (int c = 0; c < nc; c++) {
            As[lk+0][lm]=a4.x; As[lk+1][lm]=a4.y; As[lk+2][lm]=a4.z; As[lk+3][lm]=a4.w;
            Bs[lk+0][lm]=b4.x; Bs[lk+1][lm]=b4.y; Bs[lk+2][lm]=b4.z; Bs[lk+3][lm]=b4.w;
            __syncthreads();
            if (c + 1 < nc) {
                int cn = c + 1;
                if (cn < nc1) {
                    a4 = *(const float4*)(ArowA + cn*16);
                    b4 = *(const float4*)(WrowA + cn*16);
                } else {
                    int cc = cn - nc1;
                    a4 = *(const float4*)(ArowB + cc*16);
                    b4 = *(const float4*)(WrowB + cc*16);
                }
            }
#pragma unroll
            for (int kk = 0; kk < 16; kk++) {
                float4 av = *(const float4*)&As[kk][ty << 2];
                ulonglong2 bq = *(const ulonglong2*)&Bs[kk][tx << 2];
                float am[4] = {av.x, av.y, av.z, av.w};
#pragma unroll
                for (int i = 0; i < 4; i++) {
                    unsigned long long amp = pk2(am[i], am[i]);
                    acc[i][0] = fma2_(amp, bq.x, acc[i][0]);
                    acc[i][1] = fma2_(amp, bq.y, acc[i][1]);
                }
            }
            __syncthreads();
        }
        if (EPI == 0) {
#pragma unroll
            for (int i = 0; i < 4; i++) {
                int m = row0 + (ty << 2) + i;
                float c0, c1, c2, c3;
                upk2(acc[i][0], c0, c1);
                upk2(acc[i][1], c2, c3);
                float vv[4] = {c0, c1, c2, c3};
#pragma unroll
                for (int j = 0; j < 4; j++) {
                    int n = col0 + (tx << 2) + j;
                    float v = vv[j];
                    if (bias) v = __fadd_rn(v, bias[n]);
                    C[(size_t)m * N + n] = v;
                }
            }
        } else {
            const int jq = (col0 >> 2) + tx;
            float4 bh4 = *(const float4*)&bhh[col0 + (tx << 2)];
            float4 bi4;
            if (EPI == 2) bi4 = *(const float4*)&bih[col0 + (tx << 2)];
#pragma unroll
            for (int i = 0; i < 4; i++) {
                int m = row0 + (ty << 2) + i;
                float c0, c1, c2, c3;
                upk2(acc[i][0], c0, c1);
                upk2(acc[i][1], c2, c3);
                float gi, gf, gg, go;
                if (EPI == 1) {
                    float4 gx4 = *(const float4*)&gx[(size_t)m*G4_ + col0 + (tx << 2)];
                    gi = __fadd_rn(__fadd_rn(gx4.x, c0), bh4.x);
                    gf = __fadd_rn(__fadd_rn(gx4.y, c1), bh4.y);
                    gg = __fadd_rn(__fadd_rn(gx4.z, c2), bh4.z);
                    go = __fadd_rn(__fadd_rn(gx4.w, c3), bh4.w);
                } else {
                    gi = __fadd_rn(__fadd_rn(c0, bi4.x), bh4.x);
                    gf = __fadd_rn(__fadd_rn(c1, bi4.y), bh4.y);
                    gg = __fadd_rn(__fadd_rn(c2, bi4.z), bh4.z);
                    go = __fadd_rn(__fadd_rn(c3, bi4.w), bh4.w);
                }
                float iv = xla_sigmoid(gi);
                float fv = xla_sigmoid(gf);
                float gv = xla_tanh(gg);
                float ov = xla_sigmoid(go);
                size_t ci = (size_t)m * H_ + jq;
                float cn = __fadd_rn(__fmul_rn(fv, cst[ci]), __fmul_rn(iv, gv));
                float hn = __fmul_rn(ov, xla_tanh(cn));
                cst[ci] = cn;
                hout[ci] = hn;
                if (encout) encout[ci] = hn;
            }
        }
    }
}

// logits for one attention over k, with q in smem (sq) and V vector; prefetched s-loop.
__device__ __forceinline__ void attn_logits(const float* __restrict__ k, int b,
                                            const float* __restrict__ V,
                                            const T2C &K2, AttnSh* A) {
    const int tid = threadIdx.x;
    const int warp = tid >> 5, lane = tid & 31;
    float4 v0q = *(const float4*)&V[lane << 3];
    float4 v1q = *(const float4*)&V[(lane << 3) + 4];
    float4 q0q = *(const float4*)&A->sq[lane << 3];
    float4 q1q = *(const float4*)&A->sq[(lane << 3) + 4];
    int s = warp;
    float4 k0v, k1v;
    if (s < S_) {
        const float* krow = k + ((size_t)s*B_ + b)*H_ + (lane << 3);
        k0v = *(const float4*)krow;
        k1v = *(const float4*)(krow + 4);
    }
    for (; s < S_; s += 8) {
        float4 c0 = k0v, c1 = k1v;
        if (s + 8 < S_) {
            const float* krow = k + ((size_t)(s+8)*B_ + b)*H_ + (lane << 3);
            k0v = *(const float4*)krow;
            k1v = *(const float4*)(krow + 4);
        }
        float x[8], tz[8];
        x[0] = __fadd_rn(q0q.x, c0.x); x[1] = __fadd_rn(q0q.y, c0.y);
        x[2] = __fadd_rn(q0q.z, c0.z); x[3] = __fadd_rn(q0q.w, c0.w);
        x[4] = __fadd_rn(q1q.x, c1.x); x[5] = __fadd_rn(q1q.y, c1.y);
        x[6] = __fadd_rn(q1q.z, c1.z); x[7] = __fadd_rn(q1q.w, c1.w);
        tanh2(K2, x[0], x[1], tz[0], tz[1]);
        tanh2(K2, x[2], x[3], tz[2], tz[3]);
        tanh2(K2, x[4], x[5], tz[4], tz[5]);
        tanh2(K2, x[6], x[7], tz[6], tz[7]);
        float p = 0.f;
        p = fmaf(tz[0], v0q.x, p); p = fmaf(tz[1], v0q.y, p);
        p = fmaf(tz[2], v0q.z, p); p = fmaf(tz[3], v0q.w, p);
        p = fmaf(tz[4], v1q.x, p); p = fmaf(tz[5], v1q.y, p);
        p = fmaf(tz[6], v1q.z, p); p = fmaf(tz[7], v1q.w, p);
#pragma unroll
        for (int off = 16; off > 0; off >>= 1) p += __shfl_xor_sync(0xffffffffu, p, off);
        if (lane == 0) {
            float lg = __fmul_rn(10.0f, xla_tanh(p));
            A->su[s] = A->smask[s] ? -INFINITY : lg;
        }
    }
}

// q projection into sq: q[tid] = sum_k hs[k]*WqT[k][tid] + bias[tid]
__device__ __forceinline__ void q_proj(const float* __restrict__ WqT, float qbv, AttnSh* A) {
    const int tid = threadIdx.x;
    float acc = 0.f;
    const float* wp = WqT + tid;
#pragma unroll 8
    for (int kk = 0; kk < H_; kk++)
        acc = fmaf(A->hs[kk], wp[kk << 8], acc);
    A->sq[tid] = __fadd_rn(acc, qbv);
}

// fused decoder tail: glimpse attention + pointer attention + sampling, per batch
__device__ void dev_dec_tail(const float* __restrict__ hsrc,
                             const float* __restrict__ gWqT, const float* __restrict__ gbq,
                             const float* __restrict__ kgl,  const float* __restrict__ gV,
                             const float* __restrict__ pWqT, const float* __restrict__ pbq,
                             const float* __restrict__ kptr, const float* __restrict__ pV,
                             unsigned char* __restrict__ mask,
                             const unsigned* __restrict__ keys, const float* __restrict__ emb,
                             float* __restrict__ decin, float* __restrict__ out, int t,
                             AttnSh* A) {
    const int tid = threadIdx.x;
    const int warp = tid >> 5, lane = tid & 31;
    const T2C K2 = make_t2c();
    const float gqb = gbq[tid], pqb = pbq[tid];

    for (int b = blockIdx.x; b < B_; b += gridDim.x) {
        if (tid < S_) A->smask[tid] = mask[(size_t)b*S_ + tid];
        A->hs[tid] = hsrc[(size_t)b*H_ + tid];
        __syncthreads();
        // ---- glimpse ----
        q_proj(gWqT, gqb, A);
        __syncthreads();
        attn_logits(kgl, b, gV, K2, A);
        __syncthreads();
        if (warp == 0) {
            float m = -INFINITY;
#pragma unroll
            for (int r = 0; r < 4; r++) { int s = lane + (r<<5); if (s < S_) m = fmaxf(m, A->su[s]); }
#pragma unroll
            for (int off = 16; off > 0; off >>= 1) m = fmaxf(m, __shfl_xor_sync(0xffffffffu, m, off));
            float sum = 0.f;
#pragma unroll
            for (int r = 0; r < 4; r++) { int s = lane + (r<<5); if (s < S_) sum += expf(__fadd_rn(A->su[s], -m)); }
#pragma unroll
            for (int off = 16; off > 0; off >>= 1) sum += __shfl_xor_sync(0xffffffffu, sum, off);
            if (lane == 0) { A->red[0] = m; A->red[1] = sum; }
        }
        __syncthreads();
        if (tid < S_) A->ws[tid] = __fdiv_rn(expf(__fadd_rn(A->su[tid], -A->red[0])), A->red[1]);
        __syncthreads();
        {
            float acc = 0.f;
#pragma unroll 4
            for (int s = 0; s < S_; s++)
                acc = fmaf(A->ws[s], kgl[((size_t)s*B_ + b)*H_ + tid], acc);
            __syncthreads();
            A->hs[tid] = acc;       // query -> hs for pointer q-proj
        }
        __syncthreads();
        // ---- pointer ----
        q_proj(pWqT, pqb, A);
        __syncthreads();
        attn_logits(kptr, b, pV, K2, A);
        __syncthreads();
        const unsigned k0 = keys[2*t], k1 = keys[2*t+1];
        if (warp == 0) {
            float best = -INFINITY; int bi = S_; float mx = -INFINITY;
#pragma unroll
            for (int r = 0; r < 4; r++) {
                int s = lane + (r << 5);
                if (s < S_) {
                    float lv = A->su[s];
                    mx = fmaxf(mx, lv);
                    float z = __fadd_rn(lv, gumbel_at(k0, k1, (unsigned)(b*S_ + s)));
                    if (z > best) { best = z; bi = s; }
                }
            }
#pragma unroll
            for (int off = 16; off > 0; off >>= 1) {
                float oz = __shfl_xor_sync(0xffffffffu, best, off);
                int   oi = __shfl_xor_sync(0xffffffffu, bi,   off);
                if (oz > best || (oz == best && oi < bi)) { best = oz; bi = oi; }
                mx = fmaxf(mx, __shfl_xor_sync(0xffffffffu, mx, off));
            }
            float se = 0.f;
#pragma unroll
            for (int r = 0; r < 4; r++) { int s = lane + (r<<5); if (s < S_) se += expf(__fadd_rn(A->su[s], -mx)); }
#pragma unroll
            for (int off = 16; off > 0; off >>= 1) se += __shfl_xor_sync(0xffffffffu, se, off);
            if (lane == 0) {
                A->chosen = bi;
                out[(size_t)b*S_ + t] = __fadd_rn(__fadd_rn(A->su[bi], -mx), -logf(se));
                out[(size_t)BS_ + (size_t)b*S_ + t] = (float)bi;
                mask[(size_t)b*S_ + bi] = 1;
            }
        }
        __syncthreads();
        int ch = A->chosen;
        decin[(size_t)b*E_ + tid] = emb[((size_t)ch*B_ + b)*E_ + tid];
        __syncthreads();
    }
}

__global__ __launch_bounds__(256, 4)
void mega_kernel(const float* __restrict__ inp,
                 const float* __restrict__ embW, const float* __restrict__ embB,
                 const float* __restrict__ eWih, const float* __restrict__ eWhh,
                 const float* __restrict__ ebih, const float* __restrict__ ebhh,
                 const float* __restrict__ dWih, const float* __restrict__ dWhh,
                 const float* __restrict__ dbih, const float* __restrict__ dbhh,
                 const float* __restrict__ pWq,  const float* __restrict__ pbq,
                 const float* __restrict__ pWk,  const float* __restrict__ pbk,
                 const float* __restrict__ pV,
                 const float* __restrict__ gWq,  const float* __restrict__ gbq,
                 const float* __restrict__ gWk,  const float* __restrict__ gbk,
                 const float* __restrict__ gV,
                 const float* __restrict__ sos,
                 float* __restrict__ out) {
    __shared__ ShU sh;
    const int tid = threadIdx.x;
    const int gstride = gridDim.x * blockDim.x;
    const int gidx = blockIdx.x * blockDim.x + tid;

    // phase 0: init, weight permutes/transposes, keys, embedding
    for (int i = gidx; i < B_*H_; i += gstride) { g_hbuf[0][i] = 0.f; g_c[i] = 0.f; }
    for (int i = gidx; i < B_*E_; i += gstride) g_decin[i] = sos[i & (E_-1)];
    for (int i = gidx; i < B_*S_; i += gstride) g_mask[i] = 0;
    for (int idx = gidx; idx < G4_*E_; idx += gstride) {
        int row = idx >> 8, kk = idx & 255;
        int j = row >> 2, g = row & 3;
        int old = (g*H_ + j)*E_ + kk;
        g_eWih_p[idx] = eWih[old];
        g_eWhh_p[idx] = eWhh[old];
        g_dWih_p[idx] = dWih[old];
        g_dWhh_p[idx] = dWhh[old];
    }
    for (int idx = gidx; idx < H_*H_; idx += gstride) {
        int kk = idx >> 8, n = idx & 255;
        g_gWqT[idx] = gWq[n*H_ + kk];
        g_pWqT[idx] = pWq[n*H_ + kk];
    }
    for (int idx = gidx; idx < G4_; idx += gstride) {
        int j = idx >> 2, g = idx & 3;
        int old = g*H_ + j;
        g_ebih_p[idx] = ebih[old];
        g_ebhh_p[idx] = ebhh[old];
        g_dbih_p[idx] = dbih[old];
        g_dbhh_p[idx] = dbhh[old];
    }
    if (blockIdx.x == 0 && tid < S_) {
        unsigned x0 = 0u, x1 = (unsigned)tid;
        threefry(0u, 42u, x0, x1);
        g_keys[2*tid]   = x0;
        g_keys[2*tid+1] = x1;
    }
    for (int idx = gidx; idx < S_*B_*E_; idx += gstride) {
        int e = idx & (E_-1);
        int i = idx >> 8;
        int s = i >> 11;
        int b = i & (B_-1);
        float x0 = inp[((size_t)b*S_ + s)*POS_ + 0];
        float x1 = inp[((size_t)b*S_ + s)*POS_ + 1];
        float dotv = fmaf(x1, embW[e*POS_ + 1], __fmul_rn(x0, embW[e*POS_ + 0]));
        g_emb[idx] = __fadd_rn(dotv, embB[e]);
    }
    gsync();

    dev_gemm_f<0>(g_emb, g_eWih_p, E_, nullptr, nullptr, 0, g_encgx, BS_, G4_,
                  g_ebih_p, nullptr, nullptr, nullptr, nullptr, nullptr, nullptr, sh.gemm);
    gsync();

    for (int t = 0; t < S_; t++) {
        dev_gemm_f<1>(g_hbuf[t & 1], g_eWhh_p, H_, nullptr, nullptr, 0,
                      nullptr, B_, G4_, nullptr,
                      g_encgx + (size_t)t*B_*G4_, nullptr, g_ebhh_p,
                      g_c, g_hbuf[(t + 1) & 1], g_encout + (size_t)t*B_*H_, sh.gemm);
        gsync();
    }

    dev_gemm_f<0>(g_encout, pWk, H_, nullptr, nullptr, 0, g_kptr, BS_, H_,
                  pbk, nullptr, nullptr, nullptr, nullptr, nullptr, nullptr, sh.gemm);
    dev_gemm_f<0>(g_encout, gWk, H_, nullptr, nullptr, 0, g_kgl, BS_, H_,
                  gbk, nullptr, nullptr, nullptr, nullptr, nullptr, nullptr, sh.gemm);
    gsync();

    for (int t = 0; t < S_; t++) {
        dev_gemm_f<2>(g_decin, g_dWih_p, E_, g_hbuf[t & 1], g_dWhh_p, H_,
                      nullptr, B_, G4_, nullptr,
                      nullptr, g_dbih_p, g_dbhh_p,
                      g_c, g_hbuf[(t + 1) & 1], nullptr, sh.gemm);
        gsync();
        dev_dec_tail(g_hbuf[(t + 1) & 1],
                     g_gWqT, gbq, g_kgl, gV,
                     g_pWqT, pbq, g_kptr, pV,
                     g_mask, g_keys, g_emb, g_decin, out, t, &sh.attn);
        gsync();
    }
}

extern "C" void kernel_launch(void* const* d_in, const int* in_sizes, int n_in,
                              void* d_out, int out_size) {
    const float* inp  = (const float*)d_in[0];
    const float* embW = (const float*)d_in[1];
    const float* embB = (const float*)d_in[2];
    const float* eWih = (const float*)d_in[3];
    const float* eWhh = (const float*)d_in[4];
    const float* ebih = (const float*)d_in[5];
    const float* ebhh = (const float*)d_in[6];
    const float* dWih = (const float*)d_in[7];
    const float* dWhh = (const float*)d_in[8];
    const float* dbih = (const float*)d_in[9];
    const float* dbhh = (const float*)d_in[10];
    const float* pWq  = (const float*)d_in[11];
    const float* pbq  = (const float*)d_in[12];
    const float* pWk  = (const float*)d_in[13];
    const float* pbk  = (const float*)d_in[14];
    const float* pV   = (const float*)d_in[15];
    const float* gWq  = (const float*)d_in[16];
    const float* gbq  = (const float*)d_in[17];
    const float* gWk  = (const float*)d_in[18];
    const float* gbk  = (const float*)d_in[19];
    const float* gV   = (const float*)d_in[20];
    const float* sos  = (const float*)d_in[21];
    float* out = (float*)d_out;

    int sms = 0;
    cudaDeviceGetAttribute(&sms, cudaDevAttrMultiProcessorCount, 0);
    int nblk = sms * 4;

    mega_kernel<<<nblk, 256>>>(
        inp, embW, embB, eWih, eWhh, ebih, ebhh,
        dWih, dWhh, dbih, dbhh,
        pWq, pbq, pWk, pbk, pV,
        gWq, gbq, gWk, gbk, gV, sos, out);
}

// round 14
// speedup vs baseline: 1.4414x; 1.2924x over previous
#include <cuda_runtime.h>
#include <math.h>
#include <stdint.h>

#define B_    2048
#define S_    100
#define POS_  2
#define E_    256
#define H_    256
#define G4_   1024
#define BS_   (B_*S_)

__device__ float g_emb[(size_t)S_*B_*E_];
__device__ float g_encgx[(size_t)S_*B_*G4_];
__device__ float g_encout[(size_t)S_*B_*H_];
__device__ float g_kptr[(size_t)S_*B_*H_];
__device__ float g_kgl[(size_t)S_*B_*H_];
__device__ float g_hbuf[2][B_*H_];
__device__ float g_c[B_*H_];
__device__ unsigned char g_mask[B_*S_];
__device__ float g_decin[B_*E_];
__device__ unsigned g_keys[2*S_];
__device__ float g_eWih_p[G4_*E_];
__device__ float g_eWhh_p[G4_*H_];
__device__ float g_dWih_p[G4_*E_];
__device__ float g_dWhh_p[G4_*H_];
__device__ float g_ebih_p[G4_], g_ebhh_p[G4_], g_dbih_p[G4_], g_dbhh_p[G4_];
__device__ float g_gWqT[H_*H_];   // [k][n]
__device__ float g_pWqT[H_*H_];
__device__ unsigned g_cnt = 0;
__device__ unsigned g_gen = 0;

__device__ __forceinline__ void gsync() {
    __syncthreads();
    if (threadIdx.x == 0) {
        __threadfence();
        unsigned gen = *(volatile unsigned*)&g_gen;
        if (atomicAdd(&g_cnt, 1u) == gridDim.x - 1) {
            g_cnt = 0;
            __threadfence();
            *(volatile unsigned*)&g_gen = gen + 1u;
        } else {
            while (*(volatile unsigned*)&g_gen == gen) { __nanosleep(64); }
            __threadfence();
        }
    }
    __syncthreads();
}

// ---------------- packed f32x2 ----------------
__device__ __forceinline__ unsigned long long pk2(float lo, float hi) {
    unsigned long long r; asm("mov.b64 %0,{%1,%2};" : "=l"(r) : "f"(lo), "f"(hi)); return r;
}
__device__ __forceinline__ void upk2(unsigned long long v, float &lo, float &hi) {
    asm("mov.b64 {%0,%1},%2;" : "=f"(lo), "=f"(hi) : "l"(v));
}
__device__ __forceinline__ unsigned long long mul2(unsigned long long a, unsigned long long b) {
    unsigned long long d; asm("mul.rn.f32x2 %0,%1,%2;" : "=l"(d) : "l"(a), "l"(b)); return d;
}
__device__ __forceinline__ unsigned long long add2(unsigned long long a, unsigned long long b) {
    unsigned long long d; asm("add.rn.f32x2 %0,%1,%2;" : "=l"(d) : "l"(a), "l"(b)); return d;
}
__device__ __forceinline__ unsigned long long fma2_(unsigned long long a, unsigned long long b,
                                                    unsigned long long c) {
    unsigned long long d; asm("fma.rn.f32x2 %0,%1,%2,%3;" : "=l"(d) : "l"(a), "l"(b), "l"(c)); return d;
}

__device__ __forceinline__ float xla_tanh(float x) {
    const float CL = 7.90531110763549805f;
    float xc = fminf(fmaxf(x, -CL), CL);
    float x2 = __fmul_rn(xc, xc);
    float p = -2.76076847742355e-16f;
    p = __fadd_rn(__fmul_rn(x2, p),  2.00018790482477e-13f);
    p = __fadd_rn(__fmul_rn(x2, p), -8.60467152213735e-11f);
    p = __fadd_rn(__fmul_rn(x2, p),  5.12229709037114e-08f);
    p = __fadd_rn(__fmul_rn(x2, p),  1.48572235717979e-05f);
    p = __fadd_rn(__fmul_rn(x2, p),  6.37261928875436e-04f);
    p = __fadd_rn(__fmul_rn(x2, p),  4.89352455891786e-03f);
    float num = __fmul_rn(xc, p);
    float q = 1.19825839466702e-06f;
    q = __fadd_rn(__fmul_rn(x2, q),  1.18534705686654e-04f);
    q = __fadd_rn(__fmul_rn(x2, q),  2.26843463243900e-03f);
    q = __fadd_rn(__fmul_rn(x2, q),  4.89352518554385e-03f);
    float r = __fdiv_rn(num, q);
    return fabsf(x) < 0.0004f ? x : r;
}
__device__ __forceinline__ float xla_sigmoid(float x) {
    return __fdiv_rn(1.0f, __fadd_rn(1.0f, expf(-x)));
}

struct T2C { unsigned long long c[11]; };
__device__ __forceinline__ T2C make_t2c() {
    T2C t;
    t.c[0]  = pk2(-2.76076847742355e-16f, -2.76076847742355e-16f);
    t.c[1]  = pk2( 2.00018790482477e-13f,  2.00018790482477e-13f);
    t.c[2]  = pk2(-8.60467152213735e-11f, -8.60467152213735e-11f);
    t.c[3]  = pk2( 5.12229709037114e-08f,  5.12229709037114e-08f);
    t.c[4]  = pk2( 1.48572235717979e-05f,  1.48572235717979e-05f);
    t.c[5]  = pk2( 6.37261928875436e-04f,  6.37261928875436e-04f);
    t.c[6]  = pk2( 4.89352455891786e-03f,  4.89352455891786e-03f);
    t.c[7]  = pk2( 1.19825839466702e-06f,  1.19825839466702e-06f);
    t.c[8]  = pk2( 1.18534705686654e-04f,  1.18534705686654e-04f);
    t.c[9]  = pk2( 2.26843463243900e-03f,  2.26843463243900e-03f);
    t.c[10] = pk2( 4.89352518554385e-03f,  4.89352518554385e-03f);
    return t;
}
__device__ __forceinline__ void tanh2(const T2C &K, float a, float b, float &ra, float &rb) {
    const float CL = 7.90531110763549805f;
    float ca = fminf(fmaxf(a, -CL), CL);
    float cb = fminf(fmaxf(b, -CL), CL);
    unsigned long long X  = pk2(ca, cb);
    unsigned long long X2 = mul2(X, X);
    unsigned long long P  = K.c[0];
    P = add2(mul2(X2, P), K.c[1]);
    P = add2(mul2(X2, P), K.c[2]);
    P = add2(mul2(X2, P), K.c[3]);
    P = add2(mul2(X2, P), K.c[4]);
    P = add2(mul2(X2, P), K.c[5]);
    P = add2(mul2(X2, P), K.c[6]);
    unsigned long long NUM = mul2(X, P);
    unsigned long long Q = K.c[7];
    Q = add2(mul2(X2, Q), K.c[8]);
    Q = add2(mul2(X2, Q), K.c[9]);
    Q = add2(mul2(X2, Q), K.c[10]);
    float na, nb, qa, qb;
    upk2(NUM, na, nb);
    upk2(Q, qa, qb);
    float da = __fdiv_rn(na, qa);
    float db = __fdiv_rn(nb, qb);
    ra = fabsf(a) < 0.0004f ? a : da;
    rb = fabsf(b) < 0.0004f ? b : db;
}

__device__ __forceinline__ unsigned rotl32(unsigned x, int d) {
    return (x << d) | (x >> (32 - d));
}
__device__ __forceinline__ void threefry(unsigned ks0, unsigned ks1,
                                         unsigned &x0, unsigned &x1) {
    unsigned ks2 = ks0 ^ ks1 ^ 0x1BD11BDAu;
    x0 += ks0; x1 += ks1;
#define TF_R(r) { x0 += x1; x1 = rotl32(x1, r); x1 ^= x0; }
    TF_R(13) TF_R(15) TF_R(26) TF_R(6)  x0 += ks1; x1 += ks2 + 1u;
    TF_R(17) TF_R(29) TF_R(16) TF_R(24) x0 += ks2; x1 += ks0 + 2u;
    TF_R(13) TF_R(15) TF_R(26) TF_R(6)  x0 += ks0; x1 += ks1 + 3u;
    TF_R(17) TF_R(29) TF_R(16) TF_R(24) x0 += ks1; x1 += ks2 + 4u;
    TF_R(13) TF_R(15) TF_R(26) TF_R(6)  x0 += ks2; x1 += ks0 + 5u;
#undef TF_R
}
__device__ __forceinline__ float gumbel_at(unsigned k0, unsigned k1, unsigned i) {
    unsigned x0 = 0u, x1 = i;
    threefry(k0, k1, x0, x1);
    unsigned bits = x0 ^ x1;
    float f = __fadd_rn(__uint_as_float((bits >> 9) | 0x3f800000u), -1.0f);
    const float TINY = 1.17549435e-38f;
    float u = fmaxf(TINY, __fadd_rn(__fmul_rn(f, 1.0f - TINY), TINY));
    return -logf(-logf(u));
}

struct AttnSh {
    float hs4[4][H_];
    float sq4[4][H_];
    float su[112];
    float ws[112];
    float red[4];
    int   chosen;
    int   nu4[4];
    unsigned char slist[4][112];
};
union ShU {
    float gemm[2*16*68];
    AttnSh attn;
};

// ---------------- fused gemm (unchanged from R13) ----------------
template<int EPI>
__device__ void dev_gemm_f(const float* __restrict__ A, const float* __restrict__ W, int K,
                           const float* __restrict__ A2, const float* __restrict__ W2, int K2,
                           float* __restrict__ C, int M, int N,
                           const float* __restrict__ bias,
                           const float* __restrict__ gx,
                           const float* __restrict__ bih, const float* __restrict__ bhh,
                           float* __restrict__ cst, float* __restrict__ hout,
                           float* __restrict__ encout,
                           float* smem) {
    float (*As)[68] = (float(*)[68])smem;
    float (*Bs)[68] = (float(*)[68])(smem + 16*68);
    const int tid = threadIdx.x;
    const int tx = tid & 15, ty = tid >> 4;
    const int lm = tid >> 2, lk = (tid & 3) << 2;
    const int tilesN = N >> 6;
    const int tiles = (M >> 6) * tilesN;
    const int nc1 = K >> 4;
    const int nc2 = A2 ? (K2 >> 4) : 0;
    const int nc = nc1 + nc2;
    for (int tI = blockIdx.x; tI < tiles; tI += gridDim.x) {
        const int row0 = (tI / tilesN) << 6;
        const int col0 = (tI % tilesN) << 6;
        unsigned long long acc[4][2];
#pragma unroll
        for (int i = 0; i < 4; i++) { acc[i][0] = 0ull; acc[i][1] = 0ull; }
        const float* ArowA = A + (size_t)(row0 + lm) * K + lk;
        const float* WrowA = W + (size_t)(col0 + lm) * K + lk;
        const float* ArowB = A2 ? A2 + (size_t)(row0 + lm) * K2 + lk : nullptr;
        const float* WrowB = A2 ? W2 + (size_t)(col0 + lm) * K2 + lk : nullptr;
        float4 a4 = *(const float4*)ArowA;
        float4 b4 = *(const float4*)WrowA;
        for (int c = 0; c < nc; c++) {
            As[lk+0][lm]=a4.x; As[lk+1][lm]=a4.y; As[lk+2][lm]=a4.z; As[lk+3][lm]=a4.w;
            Bs[lk+0][lm]=b4.x; Bs[lk+1][lm]=b4.y; Bs[lk+2][lm]=b4.z; Bs[lk+3][lm]=b4.w;
            __syncthreads();
            if (c + 1 < nc) {
                int cn = c + 1;
                if (cn < nc1) {
                    a4 = *(const float4*)(ArowA + cn*16);
                    b4 = *(const float4*)(WrowA + cn*16);
                } else {
                    int cc = cn - nc1;
                    a4 = *(const float4*)(ArowB + cc*16);
                    b4 = *(const float4*)(WrowB + cc*16);
                }
            }
#pragma unroll
            for (int kk = 0; kk < 16; kk++) {
                float4 av = *(const float4*)&As[kk][ty << 2];
                ulonglong2 bq = *(const ulonglong2*)&Bs[kk][tx << 2];
                float am[4] = {av.x, av.y, av.z, av.w};
#pragma unroll
                for (int i = 0; i < 4; i++) {
                    unsigned long long amp = pk2(am[i], am[i]);
                    acc[i][0] = fma2_(amp, bq.x, acc[i][0]);
                    acc[i][1] = fma2_(amp, bq.y, acc[i][1]);
                }
            }
            __syncthreads();
        }
        if (EPI == 0) {
#pragma unroll
            for (int i = 0; i < 4; i++) {
                int m = row0 + (ty << 2) + i;
                float c0, c1, c2, c3;
                upk2(acc[i][0], c0, c1);
                upk2(acc[i][1], c2, c3);
                float vv[4] = {c0, c1, c2, c3};
#pragma unroll
                for (int j = 0; j < 4; j++) {
                    int n = col0 + (tx << 2) + j;
                    float v = vv[j];
                    if (bias) v = __fadd_rn(v, bias[n]);
                    C[(size_t)m * N + n] = v;
                }
            }
        } else {
            const int jq = (col0 >> 2) + tx;
            float4 bh4 = *(const float4*)&bhh[col0 + (tx << 2)];
            float4 bi4;
            if (EPI == 2) bi4 = *(const float4*)&bih[col0 + (tx << 2)];
#pragma unroll
            for (int i = 0; i < 4; i++) {
                int m = row0 + (ty << 2) + i;
                float c0, c1, c2, c3;
                upk2(acc[i][0], c0, c1);
                upk2(acc[i][1], c2, c3);
                float gi, gf, gg, go;
                if (EPI == 1) {
                    float4 gx4 = *(const float4*)&gx[(size_t)m*G4_ + col0 + (tx << 2)];
                    gi = __fadd_rn(__fadd_rn(gx4.x, c0), bh4.x);
                    gf = __fadd_rn(__fadd_rn(gx4.y, c1), bh4.y);
                    gg = __fadd_rn(__fadd_rn(gx4.z, c2), bh4.z);
                    go = __fadd_rn(__fadd_rn(gx4.w, c3), bh4.w);
                } else {
                    gi = __fadd_rn(__fadd_rn(c0, bi4.x), bh4.x);
                    gf = __fadd_rn(__fadd_rn(c1, bi4.y), bh4.y);
                    gg = __fadd_rn(__fadd_rn(c2, bi4.z), bh4.z);
                    go = __fadd_rn(__fadd_rn(c3, bi4.w), bh4.w);
                }
                float iv = xla_sigmoid(gi);
                float fv = xla_sigmoid(gf);
                float gv = xla_tanh(gg);
                float ov = xla_sigmoid(go);
                size_t ci = (size_t)m * H_ + jq;
                float cn = __fadd_rn(__fmul_rn(fv, cst[ci]), __fmul_rn(iv, gv));
                float hn = __fmul_rn(ov, xla_tanh(cn));
                cst[ci] = cn;
                hout[ci] = hn;
                if (encout) encout[ci] = hn;
            }
        }
    }
}

// batched q projection for 4 batches: sq4[i][tid] = sum_k hs4[i][k]*WqT[k][tid] + qb[tid]
__device__ __forceinline__ void qproj4(const float* __restrict__ WqT, float qbv, AttnSh* A) {
    const int tid = threadIdx.x;
    float a0 = 0.f, a1 = 0.f, a2 = 0.f, a3 = 0.f;
    const float* wp = WqT + tid;
#pragma unroll 4
    for (int kk = 0; kk < H_; kk++) {
        float w = wp[kk << 8];
        a0 = fmaf(A->hs4[0][kk], w, a0);
        a1 = fmaf(A->hs4[1][kk], w, a1);
        a2 = fmaf(A->hs4[2][kk], w, a2);
        a3 = fmaf(A->hs4[3][kk], w, a3);
    }
    A->sq4[0][tid] = __fadd_rn(a0, qbv);
    A->sq4[1][tid] = __fadd_rn(a1, qbv);
    A->sq4[2][tid] = __fadd_rn(a2, qbv);
    A->sq4[3][tid] = __fadd_rn(a3, qbv);
}

// attention logits over compacted unmasked list (masked su stay -inf; set by caller)
__device__ __forceinline__ void attn_logits_list(const float* __restrict__ k, int b,
                                                 const float* __restrict__ V,
                                                 const T2C &K2, AttnSh* A, int bi) {
    const int tid = threadIdx.x;
    const int warp = tid >> 5, lane = tid & 31;
    const int nu = A->nu4[bi];
    float4 v0q = *(const float4*)&V[lane << 3];
    float4 v1q = *(const float4*)&V[(lane << 3) + 4];
    float4 q0q = *(const float4*)&A->sq4[bi][lane << 3];
    float4 q1q = *(const float4*)&A->sq4[bi][(lane << 3) + 4];
    int j = warp;
    int scur = 0;
    float4 k0v, k1v;
    if (j < nu) {
        scur = A->slist[bi][j];
        const float* krow = k + ((size_t)scur*B_ + b)*H_ + (lane << 3);
        k0v = *(const float4*)krow;
        k1v = *(const float4*)(krow + 4);
    }
    for (; j < nu; j += 8) {
        float4 c0 = k0v, c1 = k1v;
        int sthis = scur;
        int jn = j + 8;
        if (jn < nu) {
            scur = A->slist[bi][jn];
            const float* krow = k + ((size_t)scur*B_ + b)*H_ + (lane << 3);
            k0v = *(const float4*)krow;
            k1v = *(const float4*)(krow + 4);
        }
        float x[8], tz[8];
        x[0] = __fadd_rn(q0q.x, c0.x); x[1] = __fadd_rn(q0q.y, c0.y);
        x[2] = __fadd_rn(q0q.z, c0.z); x[3] = __fadd_rn(q0q.w, c0.w);
        x[4] = __fadd_rn(q1q.x, c1.x); x[5] = __fadd_rn(q1q.y, c1.y);
        x[6] = __fadd_rn(q1q.z, c1.z); x[7] = __fadd_rn(q1q.w, c1.w);
        tanh2(K2, x[0], x[1], tz[0], tz[1]);
        tanh2(K2, x[2], x[3], tz[2], tz[3]);
        tanh2(K2, x[4], x[5], tz[4], tz[5]);
        tanh2(K2, x[6], x[7], tz[6], tz[7]);
        float p = 0.f;
        p = fmaf(tz[0], v0q.x, p); p = fmaf(tz[1], v0q.y, p);
        p = fmaf(tz[2], v0q.z, p); p = fmaf(tz[3], v0q.w, p);
        p = fmaf(tz[4], v1q.x, p); p = fmaf(tz[5], v1q.y, p);
        p = fmaf(tz[6], v1q.z, p); p = fmaf(tz[7], v1q.w, p);
#pragma unroll
        for (int off = 16; off > 0; off >>= 1) p += __shfl_xor_sync(0xffffffffu, p, off);
        if (lane == 0)
            A->su[sthis] = __fmul_rn(10.0f, xla_tanh(p));
    }
}

// fused decoder tail over quads of 4 batches
__device__ void dev_dec_tail(const float* __restrict__ hsrc,
                             const float* __restrict__ gWqT, const float* __restrict__ gbq,
                             const float* __restrict__ kgl,  const float* __restrict__ gV,
                             const float* __restrict__ pWqT, const float* __restrict__ pbq,
                             const float* __restrict__ kptr, const float* __restrict__ pV,
                             unsigned char* __restrict__ mask,
                             const unsigned* __restrict__ keys, const float* __restrict__ emb,
                             float* __restrict__ decin, float* __restrict__ out, int t,
                             AttnSh* A) {
    const int tid = threadIdx.x;
    const int warp = tid >> 5, lane = tid & 31;
    const T2C K2 = make_t2c();
    const float gqb = gbq[tid], pqb = pbq[tid];
    const unsigned kk0 = keys[2*t], kk1 = keys[2*t+1];
    const int quads = B_ >> 2;

    for (int qb = blockIdx.x; qb < quads; qb += gridDim.x) {
        const int b0 = qb << 2;
        // stage h + build compacted unmasked lists
#pragma unroll
        for (int i = 0; i < 4; i++)
            A->hs4[i][tid] = hsrc[(size_t)(b0+i)*H_ + tid];
        __syncthreads();
        if (tid < 4) {
            const unsigned char* mrow = mask + (size_t)(b0+tid)*S_;
            int nu = 0;
            for (int s = 0; s < S_; s++)
                if (!mrow[s]) A->slist[tid][nu++] = (unsigned char)s;
            A->nu4[tid] = nu;
        }
        __syncthreads();
        // ---- glimpse: batched q proj ----
        qproj4(gWqT, gqb, A);
        __syncthreads();
#pragma unroll 1
        for (int i = 0; i < 4; i++) {
            const int b = b0 + i;
            if (tid < 112) A->su[tid] = -INFINITY;
            __syncthreads();
            attn_logits_list(kgl, b, gV, K2, A, i);
            __syncthreads();
            if (warp == 0) {
                float m = -INFINITY;
#pragma unroll
                for (int r = 0; r < 4; r++) { int s = lane + (r<<5); if (s < S_) m = fmaxf(m, A->su[s]); }
#pragma unroll
                for (int off = 16; off > 0; off >>= 1) m = fmaxf(m, __shfl_xor_sync(0xffffffffu, m, off));
                float sum = 0.f;
#pragma unroll
                for (int r = 0; r < 4; r++) { int s = lane + (r<<5); if (s < S_) sum += expf(__fadd_rn(A->su[s], -m)); }
#pragma unroll
                for (int off = 16; off > 0; off >>= 1) sum += __shfl_xor_sync(0xffffffffu, sum, off);
                if (lane == 0) { A->red[0] = m; A->red[1] = sum; }
            }
            __syncthreads();
            if (tid < S_) A->ws[tid] = __fdiv_rn(expf(__fadd_rn(A->su[tid], -A->red[0])), A->red[1]);
            __syncthreads();
            float acc = 0.f;
            const int nu = A->nu4[i];
            for (int j = 0; j < nu; j++) {
                int s = A->slist[i][j];
                acc = fmaf(A->ws[s], kgl[((size_t)s*B_ + b)*H_ + tid], acc);
            }
            __syncthreads();
            A->hs4[i][tid] = acc;   // query
            __syncthreads();
        }
        // ---- pointer: batched q proj from queries ----
        qproj4(pWqT, pqb, A);
        __syncthreads();
#pragma unroll 1
        for (int i = 0; i < 4; i++) {
            const int b = b0 + i;
            if (tid < 112) A->su[tid] = -INFINITY;
            __syncthreads();
            attn_logits_list(kptr, b, pV, K2, A, i);
            __syncthreads();
            if (warp == 0) {
                float best = -INFINITY; int bi = S_; float mx = -INFINITY;
#pragma unroll
                for (int r = 0; r < 4; r++) {
                    int s = lane + (r << 5);
                    if (s < S_) {
                        float lv = A->su[s];
                        mx = fmaxf(mx, lv);
                        float z = __fadd_rn(lv, gumbel_at(kk0, kk1, (unsigned)(b*S_ + s)));
                        if (z > best) { best = z; bi = s; }
                    }
                }
#pragma unroll
                for (int off = 16; off > 0; off >>= 1) {
                    float oz = __shfl_xor_sync(0xffffffffu, best, off);
                    int   oi = __shfl_xor_sync(0xffffffffu, bi,   off);
                    if (oz > best || (oz == best && oi < bi)) { best = oz; bi = oi; }
                    mx = fmaxf(mx, __shfl_xor_sync(0xffffffffu, mx, off));
                }
                float se = 0.f;
#pragma unroll
                for (int r = 0; r < 4; r++) { int s = lane + (r<<5); if (s < S_) se += expf(__fadd_rn(A->su[s], -mx)); }
#pragma unroll
                for (int off = 16; off > 0; off >>= 1) se += __shfl_xor_sync(0xffffffffu, se, off);
                if (lane == 0) {
                    A->chosen = bi;
                    out[(size_t)b*S_ + t] = __fadd_rn(__fadd_rn(A->su[bi], -mx), -logf(se));
                    out[(size_t)BS_ + (size_t)b*S_ + t] = (float)bi;
                    mask[(size_t)b*S_ + bi] = 1;
                }
            }
            __syncthreads();
            int ch = A->chosen;
            decin[(size_t)b*E_ + tid] = emb[((size_t)ch*B_ + b)*E_ + tid];
            __syncthreads();
        }
    }
}

__global__ __launch_bounds__(256, 4)
void mega_kernel(const float* __restrict__ inp,
                 const float* __restrict__ embW, const float* __restrict__ embB,
                 const float* __restrict__ eWih, const float* __restrict__ eWhh,
                 const float* __restrict__ ebih, const float* __restrict__ ebhh,
                 const float* __restrict__ dWih, const float* __restrict__ dWhh,
                 const float* __restrict__ dbih, const float* __restrict__ dbhh,
                 const float* __restrict__ pWq,  const float* __restrict__ pbq,
                 const float* __restrict__ pWk,  const float* __restrict__ pbk,
                 const float* __restrict__ pV,
                 const float* __restrict__ gWq,  const float* __restrict__ gbq,
                 const float* __restrict__ gWk,  const float* __restrict__ gbk,
                 const float* __restrict__ gV,
                 const float* __restrict__ sos,
                 float* __restrict__ out) {
    __shared__ ShU sh;
    const int tid = threadIdx.x;
    const int gstride = gridDim.x * blockDim.x;
    const int gidx = blockIdx.x * blockDim.x + tid;

    for (int i = gidx; i < B_*H_; i += gstride) { g_hbuf[0][i] = 0.f; g_c[i] = 0.f; }
    for (int i = gidx; i < B_*E_; i += gstride) g_decin[i] = sos[i & (E_-1)];
    for (int i = gidx; i < B_*S_; i += gstride) g_mask[i] = 0;
    for (int idx = gidx; idx < G4_*E_; idx += gstride) {
        int row = idx >> 8, kk = idx & 255;
        int j = row >> 2, g = row & 3;
        int old = (g*H_ + j)*E_ + kk;
        g_eWih_p[idx] = eWih[old];
        g_eWhh_p[idx] = eWhh[old];
        g_dWih_p[idx] = dWih[old];
        g_dWhh_p[idx] = dWhh[old];
    }
    for (int idx = gidx; idx < H_*H_; idx += gstride) {
        int kk = idx >> 8, n = idx & 255;
        g_gWqT[idx] = gWq[n*H_ + kk];
        g_pWqT[idx] = pWq[n*H_ + kk];
    }
    for (int idx = gidx; idx < G4_; idx += gstride) {
        int j = idx >> 2, g = idx & 3;
        int old = g*H_ + j;
        g_ebih_p[idx] = ebih[old];
        g_ebhh_p[idx] = ebhh[old];
        g_dbih_p[idx] = dbih[old];
        g_dbhh_p[idx] = dbhh[old];
    }
    if (blockIdx.x == 0 && tid < S_) {
        unsigned x0 = 0u, x1 = (unsigned)tid;
        threefry(0u, 42u, x0, x1);
        g_keys[2*tid]   = x0;
        g_keys[2*tid+1] = x1;
    }
    for (int idx = gidx; idx < S_*B_*E_; idx += gstride) {
        int e = idx & (E_-1);
        int i = idx >> 8;
        int s = i >> 11;
        int b = i & (B_-1);
        float x0 = inp[((size_t)b*S_ + s)*POS_ + 0];
        float x1 = inp[((size_t)b*S_ + s)*POS_ + 1];
        float dotv = fmaf(x1, embW[e*POS_ + 1], __fmul_rn(x0, embW[e*POS_ + 0]));
        g_emb[idx] = __fadd_rn(dotv, embB[e]);
    }
    gsync();

    dev_gemm_f<0>(g_emb, g_eWih_p, E_, nullptr, nullptr, 0, g_encgx, BS_, G4_,
                  g_ebih_p, nullptr, nullptr, nullptr, nullptr, nullptr, nullptr, sh.gemm);
    gsync();

    for (int t = 0; t < S_; t++) {
        dev_gemm_f<1>(g_hbuf[t & 1], g_eWhh_p, H_, nullptr, nullptr, 0,
                      nullptr, B_, G4_, nullptr,
                      g_encgx + (size_t)t*B_*G4_, nullptr, g_ebhh_p,
                      g_c, g_hbuf[(t + 1) & 1], g_encout + (size_t)t*B_*H_, sh.gemm);
        gsync();
    }

    dev_gemm_f<0>(g_encout, pWk, H_, nullptr, nullptr, 0, g_kptr, BS_, H_,
                  pbk, nullptr, nullptr, nullptr, nullptr, nullptr, nullptr, sh.gemm);
    dev_gemm_f<0>(g_encout, gWk, H_, nullptr, nullptr, 0, g_kgl, BS_, H_,
                  gbk, nullptr, nullptr, nullptr, nullptr, nullptr, nullptr, sh.gemm);
    gsync();

    for (int t = 0; t < S_; t++) {
        dev_gemm_f<2>(g_decin, g_dWih_p, E_, g_hbuf[t & 1], g_dWhh_p, H_,
                      nullptr, B_, G4_, nullptr,
                      nullptr, g_dbih_p, g_dbhh_p,
                      g_c, g_hbuf[(t + 1) & 1], nullptr, sh.gemm);
        gsync();
        dev_dec_tail(g_hbuf[(t + 1) & 1],
                     g_gWqT, gbq, g_kgl, gV,
                     g_pWqT, pbq, g_kptr, pV,
                     g_mask, g_keys, g_emb, g_decin, out, t, &sh.attn);
        gsync();
    }
}

extern "C" void kernel_launch(void* const* d_in, const int* in_sizes, int n_in,
                              void* d_out, int out_size) {
    const float* inp  = (const float*)d_in[0];
    const float* embW = (const float*)d_in[1];
    const float* embB = (const float*)d_in[2];
    const float* eWih = (const float*)d_in[3];
    const float* eWhh = (const float*)d_in[4];
    const float* ebih = (const float*)d_in[5];
    const float* ebhh = (const float*)d_in[6];
    const float* dWih = (const float*)d_in[7];
    const float* dWhh = (const float*)d_in[8];
    const float* dbih = (const float*)d_in[9];
    const float* dbhh = (const float*)d_in[10];
    const float* pWq  = (const float*)d_in[11];
    const float* pbq  = (const float*)d_in[12];
    const float* pWk  = (const float*)d_in[13];
    const float* pbk  = (const float*)d_in[14];
    const float* pV   = (const float*)d_in[15];
    const float* gWq  = (const float*)d_in[16];
    const float* gbq  = (const float*)d_in[17];
    const float* gWk  = (const float*)d_in[18];
    const float* gbk  = (const float*)d_in[19];
    const float* gV   = (const float*)d_in[20];
    const float* sos  = (const float*)d_in[21];
    float* out = (float*)d_out;

    int sms = 0;
    cudaDeviceGetAttribute(&sms, cudaDevAttrMultiProcessorCount, 0);
    int nblk = sms * 4;

    mega_kernel<<<nblk, 256>>>(
        inp, embW, embB, eWih, eWhh, ebih, ebhh,
        dWih, dWhh, dbih, dbhh,
        pWq, pbq, pWk, pbk, pV,
        gWq, gbq, gWk, gbk, gV, sos, out);
}

// round 15
// speedup vs baseline: 1.4771x; 1.0248x over previous
#include <cuda_runtime.h>
#include <math.h>
#include <stdint.h>

#define B_    2048
#define S_    100
#define POS_  2
#define E_    256
#define H_    256
#define G4_   1024
#define BS_   (B_*S_)

__device__ float g_emb[(size_t)S_*B_*E_];
__device__ float g_encgx[(size_t)S_*B_*G4_];
__device__ float g_encout[(size_t)S_*B_*H_];
__device__ float g_kptr[(size_t)S_*B_*H_];
__device__ float g_kgl[(size_t)S_*B_*H_];
__device__ float g_hbuf[2][B_*H_];
__device__ float g_c[B_*H_];
__device__ unsigned char g_mask[B_*S_];
__device__ float g_decin[B_*E_];
__device__ unsigned g_keys[2*S_];
__device__ float g_eWih_p[G4_*E_];
__device__ float g_eWhh_p[G4_*H_];
__device__ float g_dWih_p[G4_*E_];
__device__ float g_dWhh_p[G4_*H_];
__device__ float g_ebih_p[G4_], g_ebhh_p[G4_], g_dbih_p[G4_], g_dbhh_p[G4_];
__device__ float g_gWqT[H_*H_];   // [k][n]
__device__ float g_pWqT[H_*H_];
__device__ unsigned g_cnt = 0;
__device__ unsigned g_gen = 0;

__device__ __forceinline__ void gsync() {
    __syncthreads();
    if (threadIdx.x == 0) {
        __threadfence();
        unsigned gen = *(volatile unsigned*)&g_gen;
        if (atomicAdd(&g_cnt, 1u) == gridDim.x - 1) {
            g_cnt = 0;
            __threadfence();
            *(volatile unsigned*)&g_gen = gen + 1u;
        } else {
            while (*(volatile unsigned*)&g_gen == gen) { __nanosleep(64); }
            __threadfence();
        }
    }
    __syncthreads();
}

// ---------------- packed f32x2 ----------------
__device__ __forceinline__ unsigned long long pk2(float lo, float hi) {
    unsigned long long r; asm("mov.b64 %0,{%1,%2};" : "=l"(r) : "f"(lo), "f"(hi)); return r;
}
__device__ __forceinline__ void upk2(unsigned long long v, float &lo, float &hi) {
    asm("mov.b64 {%0,%1},%2;" : "=f"(lo), "=f"(hi) : "l"(v));
}
__device__ __forceinline__ unsigned long long mul2(unsigned long long a, unsigned long long b) {
    unsigned long long d; asm("mul.rn.f32x2 %0,%1,%2;" : "=l"(d) : "l"(a), "l"(b)); return d;
}
__device__ __forceinline__ unsigned long long add2(unsigned long long a, unsigned long long b) {
    unsigned long long d; asm("add.rn.f32x2 %0,%1,%2;" : "=l"(d) : "l"(a), "l"(b)); return d;
}
__device__ __forceinline__ unsigned long long fma2_(unsigned long long a, unsigned long long b,
                                                    unsigned long long c) {
    unsigned long long d; asm("fma.rn.f32x2 %0,%1,%2,%3;" : "=l"(d) : "l"(a), "l"(b), "l"(c)); return d;
}

__device__ __forceinline__ float xla_tanh(float x) {
    const float CL = 7.90531110763549805f;
    float xc = fminf(fmaxf(x, -CL), CL);
    float x2 = __fmul_rn(xc, xc);
    float p = -2.76076847742355e-16f;
    p = __fadd_rn(__fmul_rn(x2, p),  2.00018790482477e-13f);
    p = __fadd_rn(__fmul_rn(x2, p), -8.60467152213735e-11f);
    p = __fadd_rn(__fmul_rn(x2, p),  5.12229709037114e-08f);
    p = __fadd_rn(__fmul_rn(x2, p),  1.48572235717979e-05f);
    p = __fadd_rn(__fmul_rn(x2, p),  6.37261928875436e-04f);
    p = __fadd_rn(__fmul_rn(x2, p),  4.89352455891786e-03f);
    float num = __fmul_rn(xc, p);
    float q = 1.19825839466702e-06f;
    q = __fadd_rn(__fmul_rn(x2, q),  1.18534705686654e-04f);
    q = __fadd_rn(__fmul_rn(x2, q),  2.26843463243900e-03f);
    q = __fadd_rn(__fmul_rn(x2, q),  4.89352518554385e-03f);
    float r = __fdiv_rn(num, q);
    return fabsf(x) < 0.0004f ? x : r;
}
__device__ __forceinline__ float xla_sigmoid(float x) {
    return __fdiv_rn(1.0f, __fadd_rn(1.0f, expf(-x)));
}

struct T2C { unsigned long long c[11]; };
__device__ __forceinline__ T2C make_t2c() {
    T2C t;
    t.c[0]  = pk2(-2.76076847742355e-16f, -2.76076847742355e-16f);
    t.c[1]  = pk2( 2.00018790482477e-13f,  2.00018790482477e-13f);
    t.c[2]  = pk2(-8.60467152213735e-11f, -8.60467152213735e-11f);
    t.c[3]  = pk2( 5.12229709037114e-08f,  5.12229709037114e-08f);
    t.c[4]  = pk2( 1.48572235717979e-05f,  1.48572235717979e-05f);
    t.c[5]  = pk2( 6.37261928875436e-04f,  6.37261928875436e-04f);
    t.c[6]  = pk2( 4.89352455891786e-03f,  4.89352455891786e-03f);
    t.c[7]  = pk2( 1.19825839466702e-06f,  1.19825839466702e-06f);
    t.c[8]  = pk2( 1.18534705686654e-04f,  1.18534705686654e-04f);
    t.c[9]  = pk2( 2.26843463243900e-03f,  2.26843463243900e-03f);
    t.c[10] = pk2( 4.89352518554385e-03f,  4.89352518554385e-03f);
    return t;
}
__device__ __forceinline__ void tanh2(const T2C &K, float a, float b, float &ra, float &rb) {
    const float CL = 7.90531110763549805f;
    float ca = fminf(fmaxf(a, -CL), CL);
    float cb = fminf(fmaxf(b, -CL), CL);
    unsigned long long X  = pk2(ca, cb);
    unsigned long long X2 = mul2(X, X);
    unsigned long long P  = K.c[0];
    P = add2(mul2(X2, P), K.c[1]);
    P = add2(mul2(X2, P), K.c[2]);
    P = add2(mul2(X2, P), K.c[3]);
    P = add2(mul2(X2, P), K.c[4]);
    P = add2(mul2(X2, P), K.c[5]);
    P = add2(mul2(X2, P), K.c[6]);
    unsigned long long NUM = mul2(X, P);
    unsigned long long Q = K.c[7];
    Q = add2(mul2(X2, Q), K.c[8]);
    Q = add2(mul2(X2, Q), K.c[9]);
    Q = add2(mul2(X2, Q), K.c[10]);
    float na, nb, qa, qb;
    upk2(NUM, na, nb);
    upk2(Q, qa, qb);
    float da = __fdiv_rn(na, qa);
    float db = __fdiv_rn(nb, qb);
    ra = fabsf(a) < 0.0004f ? a : da;
    rb = fabsf(b) < 0.0004f ? b : db;
}

__device__ __forceinline__ unsigned rotl32(unsigned x, int d) {
    return (x << d) | (x >> (32 - d));
}
__device__ __forceinline__ void threefry(unsigned ks0, unsigned ks1,
                                         unsigned &x0, unsigned &x1) {
    unsigned ks2 = ks0 ^ ks1 ^ 0x1BD11BDAu;
    x0 += ks0; x1 += ks1;
#define TF_R(r) { x0 += x1; x1 = rotl32(x1, r); x1 ^= x0; }
    TF_R(13) TF_R(15) TF_R(26) TF_R(6)  x0 += ks1; x1 += ks2 + 1u;
    TF_R(17) TF_R(29) TF_R(16) TF_R(24) x0 += ks2; x1 += ks0 + 2u;
    TF_R(13) TF_R(15) TF_R(26) TF_R(6)  x0 += ks0; x1 += ks1 + 3u;
    TF_R(17) TF_R(29) TF_R(16) TF_R(24) x0 += ks1; x1 += ks2 + 4u;
    TF_R(13) TF_R(15) TF_R(26) TF_R(6)  x0 += ks2; x1 += ks0 + 5u;
#undef TF_R
}
__device__ __forceinline__ float gumbel_at(unsigned k0, unsigned k1, unsigned i) {
    unsigned x0 = 0u, x1 = i;
    threefry(k0, k1, x0, x1);
    unsigned bits = x0 ^ x1;
    float f = __fadd_rn(__uint_as_float((bits >> 9) | 0x3f800000u), -1.0f);
    const float TINY = 1.17549435e-38f;
    float u = fmaxf(TINY, __fadd_rn(__fmul_rn(f, 1.0f - TINY), TINY));
    return -logf(-logf(u));
}

struct AttnSh {
    float hs4[4][H_];
    float sq4[4][H_];
    float su4[4][112];
    float ws4[4][112];
    float red4[4][2];
    int   chosen4[4];
    int   nu4[4];
    unsigned char slist[4][112];
};
union ShU {
    float gemm[4*16*68];   // double-buffered As/Bs
    AttnSh attn;
};

// ---------------- fused gemm, double-buffered smem (1 sync per chunk) ----------------
template<int EPI>
__device__ void dev_gemm_f(const float* __restrict__ A, const float* __restrict__ W, int K,
                           const float* __restrict__ A2, const float* __restrict__ W2, int K2,
                           float* __restrict__ C, int M, int N,
                           const float* __restrict__ bias,
                           const float* __restrict__ gx,
                           const float* __restrict__ bih, const float* __restrict__ bhh,
                           float* __restrict__ cst, float* __restrict__ hout,
                           float* __restrict__ encout,
                           float* smem) {
    // buffers: buf[p]: As = smem + p*2*16*68, Bs = +16*68
    const int tid = threadIdx.x;
    const int tx = tid & 15, ty = tid >> 4;
    const int lm = tid >> 2, lk = (tid & 3) << 2;
    const int tilesN = N >> 6;
    const int tiles = (M >> 6) * tilesN;
    const int nc1 = K >> 4;
    const int nc2 = A2 ? (K2 >> 4) : 0;
    const int nc = nc1 + nc2;
    for (int tI = blockIdx.x; tI < tiles; tI += gridDim.x) {
        const int row0 = (tI / tilesN) << 6;
        const int col0 = (tI % tilesN) << 6;
        unsigned long long acc[4][2];
#pragma unroll
        for (int i = 0; i < 4; i++) { acc[i][0] = 0ull; acc[i][1] = 0ull; }
        const float* ArowA = A + (size_t)(row0 + lm) * K + lk;
        const float* WrowA = W + (size_t)(col0 + lm) * K + lk;
        const float* ArowB = A2 ? A2 + (size_t)(row0 + lm) * K2 + lk : nullptr;
        const float* WrowB = A2 ? W2 + (size_t)(col0 + lm) * K2 + lk : nullptr;
        {   // preload chunk 0 into buffer 0
            float4 a4 = *(const float4*)ArowA;
            float4 b4 = *(const float4*)WrowA;
            float* As0 = smem;
            float* Bs0 = smem + 16*68;
            As0[(lk+0)*68+lm]=a4.x; As0[(lk+1)*68+lm]=a4.y;
            As0[(lk+2)*68+lm]=a4.z; As0[(lk+3)*68+lm]=a4.w;
            Bs0[(lk+0)*68+lm]=b4.x; Bs0[(lk+1)*68+lm]=b4.y;
            Bs0[(lk+2)*68+lm]=b4.z; Bs0[(lk+3)*68+lm]=b4.w;
        }
        __syncthreads();
        for (int c = 0; c < nc; c++) {
            float* Asc = smem + (c & 1) * (2*16*68);
            float* Bsc = Asc + 16*68;
            if (c + 1 < nc) {   // prefetch chunk c+1 into the other buffer
                int cn = c + 1;
                float4 a4, b4;
                if (cn < nc1) {
                    a4 = *(const float4*)(ArowA + cn*16);
                    b4 = *(const float4*)(WrowA + cn*16);
                } else {
                    int cc = cn - nc1;
                    a4 = *(const float4*)(ArowB + cc*16);
                    b4 = *(const float4*)(WrowB + cc*16);
                }
                float* Asn = smem + (cn & 1) * (2*16*68);
                float* Bsn = Asn + 16*68;
                Asn[(lk+0)*68+lm]=a4.x; Asn[(lk+1)*68+lm]=a4.y;
                Asn[(lk+2)*68+lm]=a4.z; Asn[(lk+3)*68+lm]=a4.w;
                Bsn[(lk+0)*68+lm]=b4.x; Bsn[(lk+1)*68+lm]=b4.y;
                Bsn[(lk+2)*68+lm]=b4.z; Bsn[(lk+3)*68+lm]=b4.w;
            }
#pragma unroll
            for (int kk = 0; kk < 16; kk++) {
                float4 av = *(const float4*)&Asc[kk*68 + (ty << 2)];
                ulonglong2 bq = *(const ulonglong2*)&Bsc[kk*68 + (tx << 2)];
                float am[4] = {av.x, av.y, av.z, av.w};
#pragma unroll
                for (int i = 0; i < 4; i++) {
                    unsigned long long amp = pk2(am[i], am[i]);
                    acc[i][0] = fma2_(amp, bq.x, acc[i][0]);
                    acc[i][1] = fma2_(amp, bq.y, acc[i][1]);
                }
            }
            __syncthreads();
        }
        if (EPI == 0) {
#pragma unroll
            for (int i = 0; i < 4; i++) {
                int m = row0 + (ty << 2) + i;
                float c0, c1, c2, c3;
                upk2(acc[i][0], c0, c1);
                upk2(acc[i][1], c2, c3);
                float vv[4] = {c0, c1, c2, c3};
#pragma unroll
                for (int j = 0; j < 4; j++) {
                    int n = col0 + (tx << 2) + j;
                    float v = vv[j];
                    if (bias) v = __fadd_rn(v, bias[n]);
                    C[(size_t)m * N + n] = v;
                }
            }
        } else {
            const int jq = (col0 >> 2) + tx;
            float4 bh4 = *(const float4*)&bhh[col0 + (tx << 2)];
            float4 bi4;
            if (EPI == 2) bi4 = *(const float4*)&bih[col0 + (tx << 2)];
#pragma unroll
            for (int i = 0; i < 4; i++) {
                int m = row0 + (ty << 2) + i;
                float c0, c1, c2, c3;
                upk2(acc[i][0], c0, c1);
                upk2(acc[i][1], c2, c3);
                float gi, gf, gg, go;
                if (EPI == 1) {
                    float4 gx4 = *(const float4*)&gx[(size_t)m*G4_ + col0 + (tx << 2)];
                    gi = __fadd_rn(__fadd_rn(gx4.x, c0), bh4.x);
                    gf = __fadd_rn(__fadd_rn(gx4.y, c1), bh4.y);
                    gg = __fadd_rn(__fadd_rn(gx4.z, c2), bh4.z);
                    go = __fadd_rn(__fadd_rn(gx4.w, c3), bh4.w);
                } else {
                    gi = __fadd_rn(__fadd_rn(c0, bi4.x), bh4.x);
                    gf = __fadd_rn(__fadd_rn(c1, bi4.y), bh4.y);
                    gg = __fadd_rn(__fadd_rn(c2, bi4.z), bh4.z);
                    go = __fadd_rn(__fadd_rn(c3, bi4.w), bh4.w);
                }
                float iv = xla_sigmoid(gi);
                float fv = xla_sigmoid(gf);
                float gv = xla_tanh(gg);
                float ov = xla_sigmoid(go);
                size_t ci = (size_t)m * H_ + jq;
                float cn = __fadd_rn(__fmul_rn(fv, cst[ci]), __fmul_rn(iv, gv));
                float hn = __fmul_rn(ov, xla_tanh(cn));
                cst[ci] = cn;
                hout[ci] = hn;
                if (encout) encout[ci] = hn;
            }
        }
    }
}

// batched q projection for 4 batches
__device__ __forceinline__ void qproj4(const float* __restrict__ WqT, float qbv, AttnSh* A) {
    const int tid = threadIdx.x;
    float a0 = 0.f, a1 = 0.f, a2 = 0.f, a3 = 0.f;
    const float* wp = WqT + tid;
#pragma unroll 4
    for (int kk = 0; kk < H_; kk++) {
        float w = wp[kk << 8];
        a0 = fmaf(A->hs4[0][kk], w, a0);
        a1 = fmaf(A->hs4[1][kk], w, a1);
        a2 = fmaf(A->hs4[2][kk], w, a2);
        a3 = fmaf(A->hs4[3][kk], w, a3);
    }
    A->sq4[0][tid] = __fadd_rn(a0, qbv);
    A->sq4[1][tid] = __fadd_rn(a1, qbv);
    A->sq4[2][tid] = __fadd_rn(a2, qbv);
    A->sq4[3][tid] = __fadd_rn(a3, qbv);
}

// logits for batch slot bi over compacted list; warp-pair (sub=0/1) splits rows j=sub, j+=2
__device__ __forceinline__ void attn_logits_pair(const float* __restrict__ k, int b,
                                                 const float* __restrict__ V,
                                                 const T2C &K2, AttnSh* A, int bi, int sub) {
    const int lane = threadIdx.x & 31;
    const int nu = A->nu4[bi];
    float4 v0q = *(const float4*)&V[lane << 3];
    float4 v1q = *(const float4*)&V[(lane << 3) + 4];
    float4 q0q = *(const float4*)&A->sq4[bi][lane << 3];
    float4 q1q = *(const float4*)&A->sq4[bi][(lane << 3) + 4];
    int j = sub;
    int scur = 0;
    float4 k0v, k1v;
    if (j < nu) {
        scur = A->slist[bi][j];
        const float* krow = k + ((size_t)scur*B_ + b)*H_ + (lane << 3);
        k0v = *(const float4*)krow;
        k1v = *(const float4*)(krow + 4);
    }
    for (; j < nu; j += 2) {
        float4 c0 = k0v, c1 = k1v;
        int sthis = scur;
        int jn = j + 2;
        if (jn < nu) {
            scur = A->slist[bi][jn];
            const float* krow = k + ((size_t)scur*B_ + b)*H_ + (lane << 3);
            k0v = *(const float4*)krow;
            k1v = *(const float4*)(krow + 4);
        }
        float x[8], tz[8];
        x[0] = __fadd_rn(q0q.x, c0.x); x[1] = __fadd_rn(q0q.y, c0.y);
        x[2] = __fadd_rn(q0q.z, c0.z); x[3] = __fadd_rn(q0q.w, c0.w);
        x[4] = __fadd_rn(q1q.x, c1.x); x[5] = __fadd_rn(q1q.y, c1.y);
        x[6] = __fadd_rn(q1q.z, c1.z); x[7] = __fadd_rn(q1q.w, c1.w);
        tanh2(K2, x[0], x[1], tz[0], tz[1]);
        tanh2(K2, x[2], x[3], tz[2], tz[3]);
        tanh2(K2, x[4], x[5], tz[4], tz[5]);
        tanh2(K2, x[6], x[7], tz[6], tz[7]);
        float p = 0.f;
        p = fmaf(tz[0], v0q.x, p); p = fmaf(tz[1], v0q.y, p);
        p = fmaf(tz[2], v0q.z, p); p = fmaf(tz[3], v0q.w, p);
        p = fmaf(tz[4], v1q.x, p); p = fmaf(tz[5], v1q.y, p);
        p = fmaf(tz[6], v1q.z, p); p = fmaf(tz[7], v1q.w, p);
#pragma unroll
        for (int off = 16; off > 0; off >>= 1) p += __shfl_xor_sync(0xffffffffu, p, off);
        if (lane == 0)
            A->su4[bi][sthis] = __fmul_rn(10.0f, xla_tanh(p));
    }
}

// fused decoder tail: warp-pair parallel over quad batches
__device__ void dev_dec_tail(const float* __restrict__ hsrc,
                             const float* __restrict__ gWqT, const float* __restrict__ gbq,
                             const float* __restrict__ kgl,  const float* __restrict__ gV,
                             const float* __restrict__ pWqT, const float* __restrict__ pbq,
                             const float* __restrict__ kptr, const float* __restrict__ pV,
                             unsigned char* __restrict__ mask,
                             const unsigned* __restrict__ keys, const float* __restrict__ emb,
                             float* __restrict__ decin, float* __restrict__ out, int t,
                             AttnSh* A) {
    const int tid = threadIdx.x;
    const int warp = tid >> 5, lane = tid & 31;
    const int bi = warp >> 1;      // batch slot owned by this warp pair
    const int sub = warp & 1;
    const int lane64 = (sub << 5) + lane;
    const T2C K2 = make_t2c();
    const float gqb = gbq[tid], pqb = pbq[tid];
    const unsigned kk0 = keys[2*t], kk1 = keys[2*t+1];
    const int quads = B_ >> 2;

    for (int qb = blockIdx.x; qb < quads; qb += gridDim.x) {
        const int b0 = qb << 2;
        const int bmine = b0 + bi;
#pragma unroll
        for (int i = 0; i < 4; i++)
            A->hs4[i][tid] = hsrc[(size_t)(b0+i)*H_ + tid];
        if (tid < 4) {
            const unsigned char* mrow = mask + (size_t)(b0+tid)*S_;
            int nu = 0;
            for (int s = 0; s < S_; s++)
                if (!mrow[s]) A->slist[tid][nu++] = (unsigned char)s;
            A->nu4[tid] = nu;
        }
        if (tid < 112) {
#pragma unroll
            for (int i = 0; i < 4; i++) A->su4[i][tid] = -INFINITY;
        }
        __syncthreads();
        // ---- glimpse ----
        qproj4(gWqT, gqb, A);
        __syncthreads();
        attn_logits_pair(kgl, bmine, gV, K2, A, bi, sub);
        __syncthreads();
        if (warp < 4) {          // warp i: softmax reduce for batch i (same pattern as R14 warp0)
            float m = -INFINITY;
#pragma unroll
            for (int r = 0; r < 4; r++) { int s = lane + (r<<5); if (s < S_) m = fmaxf(m, A->su4[warp][s]); }
#pragma unroll
            for (int off = 16; off > 0; off >>= 1) m = fmaxf(m, __shfl_xor_sync(0xffffffffu, m, off));
            float sum = 0.f;
#pragma unroll
            for (int r = 0; r < 4; r++) { int s = lane + (r<<5); if (s < S_) sum += expf(__fadd_rn(A->su4[warp][s], -m)); }
#pragma unroll
            for (int off = 16; off > 0; off >>= 1) sum += __shfl_xor_sync(0xffffffffu, sum, off);
            if (lane == 0) { A->red4[warp][0] = m; A->red4[warp][1] = sum; }
        }
        __syncthreads();
        if (warp < 4) {          // warp i: ws for batch i (elementwise; same math per element)
#pragma unroll
            for (int r = 0; r < 4; r++) {
                int s = lane + (r << 5);
                if (s < S_)
                    A->ws4[warp][s] = __fdiv_rn(expf(__fadd_rn(A->su4[warp][s], -A->red4[warp][0])),
                                                A->red4[warp][1]);
            }
        }
        __syncthreads();
        {   // weighted sum: warp pair handles its batch, 64 lanes x 4 h-elements
            float acc[4] = {0.f, 0.f, 0.f, 0.f};
            const int nu = A->nu4[bi];
            for (int j = 0; j < nu; j++) {
                int s = A->slist[bi][j];
                float w = A->ws4[bi][s];
                const float* krow = kgl + ((size_t)s*B_ + bmine)*H_;
#pragma unroll
                for (int r = 0; r < 4; r++)
                    acc[r] = fmaf(w, krow[lane64 + (r << 6)], acc[r]);
            }
            __syncthreads();
#pragma unroll
            for (int r = 0; r < 4; r++)
                A->hs4[bi][lane64 + (r << 6)] = acc[r];
        }
        if (tid < 112) {
#pragma unroll
            for (int i = 0; i < 4; i++) A->su4[i][tid] = -INFINITY;
        }
        __syncthreads();
        // ---- pointer ----
        qproj4(pWqT, pqb, A);
        __syncthreads();
        attn_logits_pair(kptr, bmine, pV, K2, A, bi, sub);
        __syncthreads();
        if (warp < 4) {          // warp i: sampling for batch i (identical pattern)
            const int b = b0 + warp;
            float best = -INFINITY; int bidx = S_; float mx = -INFINITY;
#pragma unroll
            for (int r = 0; r < 4; r++) {
                int s = lane + (r << 5);
                if (s < S_) {
                    float lv = A->su4[warp][s];
                    mx = fmaxf(mx, lv);
                    float z = __fadd_rn(lv, gumbel_at(kk0, kk1, (unsigned)(b*S_ + s)));
                    if (z > best) { best = z; bidx = s; }
                }
            }
#pragma unroll
            for (int off = 16; off > 0; off >>= 1) {
                float oz = __shfl_xor_sync(0xffffffffu, best, off);
                int   oi = __shfl_xor_sync(0xffffffffu, bidx, off);
                if (oz > best || (oz == best && oi < bidx)) { best = oz; bidx = oi; }
                mx = fmaxf(mx, __shfl_xor_sync(0xffffffffu, mx, off));
            }
            float se = 0.f;
#pragma unroll
            for (int r = 0; r < 4; r++) { int s = lane + (r<<5); if (s < S_) se += expf(__fadd_rn(A->su4[warp][s], -mx)); }
#pragma unroll
            for (int off = 16; off > 0; off >>= 1) se += __shfl_xor_sync(0xffffffffu, se, off);
            if (lane == 0) {
                A->chosen4[warp] = bidx;
                out[(size_t)b*S_ + t] = __fadd_rn(__fadd_rn(A->su4[warp][bidx], -mx), -logf(se));
                out[(size_t)BS_ + (size_t)b*S_ + t] = (float)bidx;
                mask[(size_t)b*S_ + bidx] = 1;
            }
        }
        __syncthreads();
        {   // decin: warp pair copies its batch
            int ch = A->chosen4[bi];
            const float* src = emb + ((size_t)ch*B_ + bmine)*E_;
            float* dst = decin + (size_t)bmine*E_;
#pragma unroll
            for (int r = 0; r < 4; r++)
                dst[lane64 + (r << 6)] = src[lane64 + (r << 6)];
        }
        __syncthreads();
    }
}

__global__ __launch_bounds__(256, 4)
void mega_kernel(const float* __restrict__ inp,
                 const float* __restrict__ embW, const float* __restrict__ embB,
                 const float* __restrict__ eWih, const float* __restrict__ eWhh,
                 const float* __restrict__ ebih, const float* __restrict__ ebhh,
                 const float* __restrict__ dWih, const float* __restrict__ dWhh,
                 const float* __restrict__ dbih, const float* __restrict__ dbhh,
                 const float* __restrict__ pWq,  const float* __restrict__ pbq,
                 const float* __restrict__ pWk,  const float* __restrict__ pbk,
                 const float* __restrict__ pV,
                 const float* __restrict__ gWq,  const float* __restrict__ gbq,
                 const float* __restrict__ gWk,  const float* __restrict__ gbk,
                 const float* __restrict__ gV,
                 const float* __restrict__ sos,
                 float* __restrict__ out) {
    __shared__ ShU sh;
    const int tid = threadIdx.x;
    const int gstride = gridDim.x * blockDim.x;
    const int gidx = blockIdx.x * blockDim.x + tid;

    for (int i = gidx; i < B_*H_; i += gstride) { g_hbuf[0][i] = 0.f; g_c[i] = 0.f; }
    for (int i = gidx; i < B_*E_; i += gstride) g_decin[i] = sos[i & (E_-1)];
    for (int i = gidx; i < B_*S_; i += gstride) g_mask[i] = 0;
    for (int idx = gidx; idx < G4_*E_; idx += gstride) {
        int row = idx >> 8, kk = idx & 255;
        int j = row >> 2, g = row & 3;
        int old = (g*H_ + j)*E_ + kk;
        g_eWih_p[idx] = eWih[old];
        g_eWhh_p[idx] = eWhh[old];
        g_dWih_p[idx] = dWih[old];
        g_dWhh_p[idx] = dWhh[old];
    }
    for (int idx = gidx; idx < H_*H_; idx += gstride) {
        int kk = idx >> 8, n = idx & 255;
        g_gWqT[idx] = gWq[n*H_ + kk];
        g_pWqT[idx] = pWq[n*H_ + kk];
    }
    for (int idx = gidx; idx < G4_; idx += gstride) {
        int j = idx >> 2, g = idx & 3;
        int old = g*H_ + j;
        g_ebih_p[idx] = ebih[old];
        g_ebhh_p[idx] = ebhh[old];
        g_dbih_p[idx] = dbih[old];
        g_dbhh_p[idx] = dbhh[old];
    }
    if (blockIdx.x == 0 && tid < S_) {
        unsigned x0 = 0u, x1 = (unsigned)tid;
        threefry(0u, 42u, x0, x1);
        g_keys[2*tid]   = x0;
        g_keys[2*tid+1] = x1;
    }
    for (int idx = gidx; idx < S_*B_*E_; idx += gstride) {
        int e = idx & (E_-1);
        int i = idx >> 8;
        int s = i >> 11;
        int b = i & (B_-1);
        float x0 = inp[((size_t)b*S_ + s)*POS_ + 0];
        float x1 = inp[((size_t)b*S_ + s)*POS_ + 1];
        float dotv = fmaf(x1, embW[e*POS_ + 1], __fmul_rn(x0, embW[e*POS_ + 0]));
        g_emb[idx] = __fadd_rn(dotv, embB[e]);
    }
    gsync();

    dev_gemm_f<0>(g_emb, g_eWih_p, E_, nullptr, nullptr, 0, g_encgx, BS_, G4_,
                  g_ebih_p, nullptr, nullptr, nullptr, nullptr, nullptr, nullptr, sh.gemm);
    gsync();

    for (int t = 0; t < S_; t++) {
        dev_gemm_f<1>(g_hbuf[t & 1], g_eWhh_p, H_, nullptr, nullptr, 0,
                      nullptr, B_, G4_, nullptr,
                      g_encgx + (size_t)t*B_*G4_, nullptr, g_ebhh_p,
                      g_c, g_hbuf[(t + 1) & 1], g_encout + (size_t)t*B_*H_, sh.gemm);
        gsync();
    }

    dev_gemm_f<0>(g_encout, pWk, H_, nullptr, nullptr, 0, g_kptr, BS_, H_,
                  pbk, nullptr, nullptr, nullptr, nullptr, nullptr, nullptr, sh.gemm);
    dev_gemm_f<0>(g_encout, gWk, H_, nullptr, nullptr, 0, g_kgl, BS_, H_,
                  gbk, nullptr, nullptr, nullptr, nullptr, nullptr, nullptr, sh.gemm);
    gsync();

    for (int t = 0; t < S_; t++) {
        dev_gemm_f<2>(g_decin, g_dWih_p, E_, g_hbuf[t & 1], g_dWhh_p, H_,
                      nullptr, B_, G4_, nullptr,
                      nullptr, g_dbih_p, g_dbhh_p,
                      g_c, g_hbuf[(t + 1) & 1], nullptr, sh.gemm);
        gsync();
        dev_dec_tail(g_hbuf[(t + 1) & 1],
                     g_gWqT, gbq, g_kgl, gV,
                     g_pWqT, pbq, g_kptr, pV,
                     g_mask, g_keys, g_emb, g_decin, out, t, &sh.attn);
        gsync();
    }
}

extern "C" void kernel_launch(void* const* d_in, const int* in_sizes, int n_in,
                              void* d_out, int out_size) {
    const float* inp  = (const float*)d_in[0];
    const float* embW = (const float*)d_in[1];
    const float* embB = (const float*)d_in[2];
    const float* eWih = (const float*)d_in[3];
    const float* eWhh = (const float*)d_in[4];
    const float* ebih = (const float*)d_in[5];
    const float* ebhh = (const float*)d_in[6];
    const float* dWih = (const float*)d_in[7];
    const float* dWhh = (const float*)d_in[8];
    const float* dbih = (const float*)d_in[9];
    const float* dbhh = (const float*)d_in[10];
    const float* pWq  = (const float*)d_in[11];
    const float* pbq  = (const float*)d_in[12];
    const float* pWk  = (const float*)d_in[13];
    const float* pbk  = (const float*)d_in[14];
    const float* pV   = (const float*)d_in[15];
    const float* gWq  = (const float*)d_in[16];
    const float* gbq  = (const float*)d_in[17];
    const float* gWk  = (const float*)d_in[18];
    const float* gbk  = (const float*)d_in[19];
    const float* gV   = (const float*)d_in[20];
    const float* sos  = (const float*)d_in[21];
    float* out = (float*)d_out;

    int sms = 0;
    cudaDeviceGetAttribute(&sms, cudaDevAttrMultiProcessorCount, 0);
    int nblk = sms * 4;

    mega_kernel<<<nblk, 256>>>(
        inp, embW, embB, eWih, eWhh, ebih, ebhh,
        dWih, dWhh, dbih, dbhh,
        pWq, pbq, pWk, pbk, pV,
        gWq, gbq, gWk, gbk, gV, sos, out);
}

// round 16
// speedup vs baseline: 1.5530x; 1.0514x over previous
#include <cuda_runtime.h>
#include <math.h>
#include <stdint.h>

#define B_    2048
#define S_    100
#define POS_  2
#define E_    256
#define H_    256
#define G4_   1024
#define BS_   (B_*S_)

__device__ float g_emb[(size_t)S_*B_*E_];
__device__ float g_encgx[(size_t)S_*B_*G4_];
__device__ float g_encout[(size_t)S_*B_*H_];
__device__ float g_kptr[(size_t)S_*B_*H_];
__device__ float g_kgl[(size_t)S_*B_*H_];
__device__ float g_hbuf[2][B_*H_];
__device__ float g_c[B_*H_];
__device__ unsigned char g_mask[B_*S_];
__device__ float g_decin[B_*E_];
__device__ unsigned g_keys[2*S_];
__device__ float g_eWih_p[G4_*E_];
__device__ float g_eWhh_p[G4_*H_];
__device__ float g_dWih_p[G4_*E_];
__device__ float g_dWhh_p[G4_*H_];
__device__ float g_ebih_p[G4_], g_ebhh_p[G4_], g_dbih_p[G4_], g_dbhh_p[G4_];
__device__ float g_gWqT[H_*H_];   // [k][n]
__device__ float g_pWqT[H_*H_];
__device__ unsigned g_cnt = 0;
__device__ unsigned g_gen = 0;

__device__ __forceinline__ void gsync() {
    __syncthreads();
    if (threadIdx.x == 0) {
        __threadfence();
        unsigned gen = *(volatile unsigned*)&g_gen;
        if (atomicAdd(&g_cnt, 1u) == gridDim.x - 1) {
            g_cnt = 0;
            __threadfence();
            *(volatile unsigned*)&g_gen = gen + 1u;
        } else {
            while (*(volatile unsigned*)&g_gen == gen) { __nanosleep(64); }
            __threadfence();
        }
    }
    __syncthreads();
}

// ---------------- packed f32x2 ----------------
__device__ __forceinline__ unsigned long long pk2(float lo, float hi) {
    unsigned long long r; asm("mov.b64 %0,{%1,%2};" : "=l"(r) : "f"(lo), "f"(hi)); return r;
}
__device__ __forceinline__ void upk2(unsigned long long v, float &lo, float &hi) {
    asm("mov.b64 {%0,%1},%2;" : "=f"(lo), "=f"(hi) : "l"(v));
}
__device__ __forceinline__ unsigned long long mul2(unsigned long long a, unsigned long long b) {
    unsigned long long d; asm("mul.rn.f32x2 %0,%1,%2;" : "=l"(d) : "l"(a), "l"(b)); return d;
}
__device__ __forceinline__ unsigned long long add2(unsigned long long a, unsigned long long b) {
    unsigned long long d; asm("add.rn.f32x2 %0,%1,%2;" : "=l"(d) : "l"(a), "l"(b)); return d;
}
__device__ __forceinline__ unsigned long long fma2_(unsigned long long a, unsigned long long b,
                                                    unsigned long long c) {
    unsigned long long d; asm("fma.rn.f32x2 %0,%1,%2,%3;" : "=l"(d) : "l"(a), "l"(b), "l"(c)); return d;
}

__device__ __forceinline__ float xla_tanh(float x) {
    const float CL = 7.90531110763549805f;
    float xc = fminf(fmaxf(x, -CL), CL);
    float x2 = __fmul_rn(xc, xc);
    float p = -2.76076847742355e-16f;
    p = __fadd_rn(__fmul_rn(x2, p),  2.00018790482477e-13f);
    p = __fadd_rn(__fmul_rn(x2, p), -8.60467152213735e-11f);
    p = __fadd_rn(__fmul_rn(x2, p),  5.12229709037114e-08f);
    p = __fadd_rn(__fmul_rn(x2, p),  1.48572235717979e-05f);
    p = __fadd_rn(__fmul_rn(x2, p),  6.37261928875436e-04f);
    p = __fadd_rn(__fmul_rn(x2, p),  4.89352455891786e-03f);
    float num = __fmul_rn(xc, p);
    float q = 1.19825839466702e-06f;
    q = __fadd_rn(__fmul_rn(x2, q),  1.18534705686654e-04f);
    q = __fadd_rn(__fmul_rn(x2, q),  2.26843463243900e-03f);
    q = __fadd_rn(__fmul_rn(x2, q),  4.89352518554385e-03f);
    float r = __fdiv_rn(num, q);
    return fabsf(x) < 0.0004f ? x : r;
}
__device__ __forceinline__ float xla_sigmoid(float x) {
    return __fdiv_rn(1.0f, __fadd_rn(1.0f, expf(-x)));
}

struct T2C { unsigned long long c[11]; };
__device__ __forceinline__ T2C make_t2c() {
    T2C t;
    t.c[0]  = pk2(-2.76076847742355e-16f, -2.76076847742355e-16f);
    t.c[1]  = pk2( 2.00018790482477e-13f,  2.00018790482477e-13f);
    t.c[2]  = pk2(-8.60467152213735e-11f, -8.60467152213735e-11f);
    t.c[3]  = pk2( 5.12229709037114e-08f,  5.12229709037114e-08f);
    t.c[4]  = pk2( 1.48572235717979e-05f,  1.48572235717979e-05f);
    t.c[5]  = pk2( 6.37261928875436e-04f,  6.37261928875436e-04f);
    t.c[6]  = pk2( 4.89352455891786e-03f,  4.89352455891786e-03f);
    t.c[7]  = pk2( 1.19825839466702e-06f,  1.19825839466702e-06f);
    t.c[8]  = pk2( 1.18534705686654e-04f,  1.18534705686654e-04f);
    t.c[9]  = pk2( 2.26843463243900e-03f,  2.26843463243900e-03f);
    t.c[10] = pk2( 4.89352518554385e-03f,  4.89352518554385e-03f);
    return t;
}
__device__ __forceinline__ void tanh2(const T2C &K, float a, float b, float &ra, float &rb) {
    const float CL = 7.90531110763549805f;
    float ca = fminf(fmaxf(a, -CL), CL);
    float cb = fminf(fmaxf(b, -CL), CL);
    unsigned long long X  = pk2(ca, cb);
    unsigned long long X2 = mul2(X, X);
    unsigned long long P  = K.c[0];
    P = add2(mul2(X2, P), K.c[1]);
    P = add2(mul2(X2, P), K.c[2]);
    P = add2(mul2(X2, P), K.c[3]);
    P = add2(mul2(X2, P), K.c[4]);
    P = add2(mul2(X2, P), K.c[5]);
    P = add2(mul2(X2, P), K.c[6]);
    unsigned long long NUM = mul2(X, P);
    unsigned long long Q = K.c[7];
    Q = add2(mul2(X2, Q), K.c[8]);
    Q = add2(mul2(X2, Q), K.c[9]);
    Q = add2(mul2(X2, Q), K.c[10]);
    float na, nb, qa, qb;
    upk2(NUM, na, nb);
    upk2(Q, qa, qb);
    float da = __fdiv_rn(na, qa);
    float db = __fdiv_rn(nb, qb);
    ra = fabsf(a) < 0.0004f ? a : da;
    rb = fabsf(b) < 0.0004f ? b : db;
}

__device__ __forceinline__ unsigned rotl32(unsigned x, int d) {
    return (x << d) | (x >> (32 - d));
}
__device__ __forceinline__ void threefry(unsigned ks0, unsigned ks1,
                                         unsigned &x0, unsigned &x1) {
    unsigned ks2 = ks0 ^ ks1 ^ 0x1BD11BDAu;
    x0 += ks0; x1 += ks1;
#define TF_R(r) { x0 += x1; x1 = rotl32(x1, r); x1 ^= x0; }
    TF_R(13) TF_R(15) TF_R(26) TF_R(6)  x0 += ks1; x1 += ks2 + 1u;
    TF_R(17) TF_R(29) TF_R(16) TF_R(24) x0 += ks2; x1 += ks0 + 2u;
    TF_R(13) TF_R(15) TF_R(26) TF_R(6)  x0 += ks0; x1 += ks1 + 3u;
    TF_R(17) TF_R(29) TF_R(16) TF_R(24) x0 += ks1; x1 += ks2 + 4u;
    TF_R(13) TF_R(15) TF_R(26) TF_R(6)  x0 += ks2; x1 += ks0 + 5u;
#undef TF_R
}
__device__ __forceinline__ float gumbel_at(unsigned k0, unsigned k1, unsigned i) {
    unsigned x0 = 0u, x1 = i;
    threefry(k0, k1, x0, x1);
    unsigned bits = x0 ^ x1;
    float f = __fadd_rn(__uint_as_float((bits >> 9) | 0x3f800000u), -1.0f);
    const float TINY = 1.17549435e-38f;
    float u = fmaxf(TINY, __fadd_rn(__fmul_rn(f, 1.0f - TINY), TINY));
    return -logf(-logf(u));
}

struct AttnSh {
    alignas(16) float hsI[H_][4];   // interleaved quad h-vectors
    float sq4[4][H_];
    float su4[4][112];
    float ws4[4][112];
    float red4[4][2];
    int   chosen4[4];
    int   nu4[4];
    unsigned char slist[4][112];
};
union ShU {
    float gemm[4*16*68];   // double-buffered As/Bs
    AttnSh attn;
};

// ---------------- fused gemm, double-buffered smem ----------------
template<int EPI>
__device__ void dev_gemm_f(const float* __restrict__ A, const float* __restrict__ W, int K,
                           const float* __restrict__ A2, const float* __restrict__ W2, int K2,
                           float* __restrict__ C, int M, int N,
                           const float* __restrict__ bias,
                           const float* __restrict__ gx,
                           const float* __restrict__ bih, const float* __restrict__ bhh,
                           float* __restrict__ cst, float* __restrict__ hout,
                           float* __restrict__ encout,
                           float* smem) {
    const int tid = threadIdx.x;
    const int tx = tid & 15, ty = tid >> 4;
    const int lm = tid >> 2, lk = (tid & 3) << 2;
    const int tilesN = N >> 6;
    const int tiles = (M >> 6) * tilesN;
    const int nc1 = K >> 4;
    const int nc2 = A2 ? (K2 >> 4) : 0;
    const int nc = nc1 + nc2;
    for (int tI = blockIdx.x; tI < tiles; tI += gridDim.x) {
        const int row0 = (tI / tilesN) << 6;
        const int col0 = (tI % tilesN) << 6;
        unsigned long long acc[4][2];
#pragma unroll
        for (int i = 0; i < 4; i++) { acc[i][0] = 0ull; acc[i][1] = 0ull; }
        const float* ArowA = A + (size_t)(row0 + lm) * K + lk;
        const float* WrowA = W + (size_t)(col0 + lm) * K + lk;
        const float* ArowB = A2 ? A2 + (size_t)(row0 + lm) * K2 + lk : nullptr;
        const float* WrowB = A2 ? W2 + (size_t)(col0 + lm) * K2 + lk : nullptr;
        {
            float4 a4 = *(const float4*)ArowA;
            float4 b4 = *(const float4*)WrowA;
            float* As0 = smem;
            float* Bs0 = smem + 16*68;
            As0[(lk+0)*68+lm]=a4.x; As0[(lk+1)*68+lm]=a4.y;
            As0[(lk+2)*68+lm]=a4.z; As0[(lk+3)*68+lm]=a4.w;
            Bs0[(lk+0)*68+lm]=b4.x; Bs0[(lk+1)*68+lm]=b4.y;
            Bs0[(lk+2)*68+lm]=b4.z; Bs0[(lk+3)*68+lm]=b4.w;
        }
        __syncthreads();
        for (int c = 0; c < nc; c++) {
            float* Asc = smem + (c & 1) * (2*16*68);
            float* Bsc = Asc + 16*68;
            if (c + 1 < nc) {
                int cn = c + 1;
                float4 a4, b4;
                if (cn < nc1) {
                    a4 = *(const float4*)(ArowA + cn*16);
                    b4 = *(const float4*)(WrowA + cn*16);
                } else {
                    int cc = cn - nc1;
                    a4 = *(const float4*)(ArowB + cc*16);
                    b4 = *(const float4*)(WrowB + cc*16);
                }
                float* Asn = smem + (cn & 1) * (2*16*68);
                float* Bsn = Asn + 16*68;
                Asn[(lk+0)*68+lm]=a4.x; Asn[(lk+1)*68+lm]=a4.y;
                Asn[(lk+2)*68+lm]=a4.z; Asn[(lk+3)*68+lm]=a4.w;
                Bsn[(lk+0)*68+lm]=b4.x; Bsn[(lk+1)*68+lm]=b4.y;
                Bsn[(lk+2)*68+lm]=b4.z; Bsn[(lk+3)*68+lm]=b4.w;
            }
#pragma unroll
            for (int kk = 0; kk < 16; kk++) {
                float4 av = *(const float4*)&Asc[kk*68 + (ty << 2)];
                ulonglong2 bq = *(const ulonglong2*)&Bsc[kk*68 + (tx << 2)];
                float am[4] = {av.x, av.y, av.z, av.w};
#pragma unroll
                for (int i = 0; i < 4; i++) {
                    unsigned long long amp = pk2(am[i], am[i]);
                    acc[i][0] = fma2_(amp, bq.x, acc[i][0]);
                    acc[i][1] = fma2_(amp, bq.y, acc[i][1]);
                }
            }
            __syncthreads();
        }
        if (EPI == 0) {
#pragma unroll
            for (int i = 0; i < 4; i++) {
                int m = row0 + (ty << 2) + i;
                float c0, c1, c2, c3;
                upk2(acc[i][0], c0, c1);
                upk2(acc[i][1], c2, c3);
                float vv[4] = {c0, c1, c2, c3};
#pragma unroll
                for (int j = 0; j < 4; j++) {
                    int n = col0 + (tx << 2) + j;
                    float v = vv[j];
                    if (bias) v = __fadd_rn(v, bias[n]);
                    C[(size_t)m * N + n] = v;
                }
            }
        } else {
            const int jq = (col0 >> 2) + tx;
            float4 bh4 = *(const float4*)&bhh[col0 + (tx << 2)];
            float4 bi4;
            if (EPI == 2) bi4 = *(const float4*)&bih[col0 + (tx << 2)];
#pragma unroll
            for (int i = 0; i < 4; i++) {
                int m = row0 + (ty << 2) + i;
                float c0, c1, c2, c3;
                upk2(acc[i][0], c0, c1);
                upk2(acc[i][1], c2, c3);
                float gi, gf, gg, go;
                if (EPI == 1) {
                    float4 gx4 = *(const float4*)&gx[(size_t)m*G4_ + col0 + (tx << 2)];
                    gi = __fadd_rn(__fadd_rn(gx4.x, c0), bh4.x);
                    gf = __fadd_rn(__fadd_rn(gx4.y, c1), bh4.y);
                    gg = __fadd_rn(__fadd_rn(gx4.z, c2), bh4.z);
                    go = __fadd_rn(__fadd_rn(gx4.w, c3), bh4.w);
                } else {
                    gi = __fadd_rn(__fadd_rn(c0, bi4.x), bh4.x);
                    gf = __fadd_rn(__fadd_rn(c1, bi4.y), bh4.y);
                    gg = __fadd_rn(__fadd_rn(c2, bi4.z), bh4.z);
                    go = __fadd_rn(__fadd_rn(c3, bi4.w), bh4.w);
                }
                float iv = xla_sigmoid(gi);
                float fv = xla_sigmoid(gf);
                float gv = xla_tanh(gg);
                float ov = xla_sigmoid(go);
                size_t ci = (size_t)m * H_ + jq;
                float cn = __fadd_rn(__fmul_rn(fv, cst[ci]), __fmul_rn(iv, gv));
                float hn = __fmul_rn(ov, xla_tanh(cn));
                cst[ci] = cn;
                hout[ci] = hn;
                if (encout) encout[ci] = hn;
            }
        }
    }
}

// batched q projection, interleaved hs: one LDS.128 serves all 4 batches per k
__device__ __forceinline__ void qproj4(const float* __restrict__ WqT, float qbv, AttnSh* A) {
    const int tid = threadIdx.x;
    unsigned long long acc01 = 0ull, acc23 = 0ull;
    const float* wp = WqT + tid;
#pragma unroll 8
    for (int kk = 0; kk < H_; kk++) {
        float w = wp[kk << 8];
        unsigned long long wpk = pk2(w, w);
        ulonglong2 hq = *(const ulonglong2*)&A->hsI[kk][0];
        acc01 = fma2_(hq.x, wpk, acc01);
        acc23 = fma2_(hq.y, wpk, acc23);
    }
    float a0, a1, a2, a3;
    upk2(acc01, a0, a1);
    upk2(acc23, a2, a3);
    A->sq4[0][tid] = __fadd_rn(a0, qbv);
    A->sq4[1][tid] = __fadd_rn(a1, qbv);
    A->sq4[2][tid] = __fadd_rn(a2, qbv);
    A->sq4[3][tid] = __fadd_rn(a3, qbv);
}

// logits for batch slot bi over compacted list; warp-pair (sub=0/1) splits rows
__device__ __forceinline__ void attn_logits_pair(const float* __restrict__ k, int b,
                                                 const float* __restrict__ V,
                                                 const T2C &K2, AttnSh* A, int bi, int sub) {
    const int lane = threadIdx.x & 31;
    const int nu = A->nu4[bi];
    float4 v0q = *(const float4*)&V[lane << 3];
    float4 v1q = *(const float4*)&V[(lane << 3) + 4];
    float4 q0q = *(const float4*)&A->sq4[bi][lane << 3];
    float4 q1q = *(const float4*)&A->sq4[bi][(lane << 3) + 4];
    int j = sub;
    int scur = 0;
    float4 k0v, k1v;
    if (j < nu) {
        scur = A->slist[bi][j];
        const float* krow = k + ((size_t)scur*B_ + b)*H_ + (lane << 3);
        k0v = *(const float4*)krow;
        k1v = *(const float4*)(krow + 4);
    }
    for (; j < nu; j += 2) {
        float4 c0 = k0v, c1 = k1v;
        int sthis = scur;
        int jn = j + 2;
        if (jn < nu) {
            scur = A->slist[bi][jn];
            const float* krow = k + ((size_t)scur*B_ + b)*H_ + (lane << 3);
            k0v = *(const float4*)krow;
            k1v = *(const float4*)(krow + 4);
        }
        float x[8], tz[8];
        x[0] = __fadd_rn(q0q.x, c0.x); x[1] = __fadd_rn(q0q.y, c0.y);
        x[2] = __fadd_rn(q0q.z, c0.z); x[3] = __fadd_rn(q0q.w, c0.w);
        x[4] = __fadd_rn(q1q.x, c1.x); x[5] = __fadd_rn(q1q.y, c1.y);
        x[6] = __fadd_rn(q1q.z, c1.z); x[7] = __fadd_rn(q1q.w, c1.w);
        tanh2(K2, x[0], x[1], tz[0], tz[1]);
        tanh2(K2, x[2], x[3], tz[2], tz[3]);
        tanh2(K2, x[4], x[5], tz[4], tz[5]);
        tanh2(K2, x[6], x[7], tz[6], tz[7]);
        float p = 0.f;
        p = fmaf(tz[0], v0q.x, p); p = fmaf(tz[1], v0q.y, p);
        p = fmaf(tz[2], v0q.z, p); p = fmaf(tz[3], v0q.w, p);
        p = fmaf(tz[4], v1q.x, p); p = fmaf(tz[5], v1q.y, p);
        p = fmaf(tz[6], v1q.z, p); p = fmaf(tz[7], v1q.w, p);
#pragma unroll
        for (int off = 16; off > 0; off >>= 1) p += __shfl_xor_sync(0xffffffffu, p, off);
        if (lane == 0)
            A->su4[bi][sthis] = __fmul_rn(10.0f, xla_tanh(p));
    }
}

// fused decoder tail: warp-pair parallel over quad batches
__device__ void dev_dec_tail(const float* __restrict__ hsrc,
                             const float* __restrict__ gWqT, const float* __restrict__ gbq,
                             const float* __restrict__ kgl,  const float* __restrict__ gV,
                             const float* __restrict__ pWqT, const float* __restrict__ pbq,
                             const float* __restrict__ kptr, const float* __restrict__ pV,
                             unsigned char* __restrict__ mask,
                             const unsigned* __restrict__ keys, const float* __restrict__ emb,
                             float* __restrict__ decin, float* __restrict__ out, int t,
                             AttnSh* A) {
    const int tid = threadIdx.x;
    const int warp = tid >> 5, lane = tid & 31;
    const int bi = warp >> 1;
    const int sub = warp & 1;
    const int lane64 = (sub << 5) + lane;
    const T2C K2 = make_t2c();
    const float gqb = gbq[tid], pqb = pbq[tid];
    const unsigned kk0 = keys[2*t], kk1 = keys[2*t+1];
    const int quads = B_ >> 2;

    for (int qb = blockIdx.x; qb < quads; qb += gridDim.x) {
        const int b0 = qb << 2;
        const int bmine = b0 + bi;
        {
            float4 hv;
            hv.x = hsrc[(size_t)(b0+0)*H_ + tid];
            hv.y = hsrc[(size_t)(b0+1)*H_ + tid];
            hv.z = hsrc[(size_t)(b0+2)*H_ + tid];
            hv.w = hsrc[(size_t)(b0+3)*H_ + tid];
            *(float4*)&A->hsI[tid][0] = hv;
        }
        if (tid < 4) {
            const unsigned char* mrow = mask + (size_t)(b0+tid)*S_;
            int nu = 0;
            for (int s = 0; s < S_; s++)
                if (!mrow[s]) A->slist[tid][nu++] = (unsigned char)s;
            A->nu4[tid] = nu;
        }
        if (tid < 112) {
#pragma unroll
            for (int i = 0; i < 4; i++) A->su4[i][tid] = -INFINITY;
        }
        __syncthreads();
        // ---- glimpse ----
        qproj4(gWqT, gqb, A);
        __syncthreads();
        attn_logits_pair(kgl, bmine, gV, K2, A, bi, sub);
        __syncthreads();
        if (warp < 4) {
            float m = -INFINITY;
#pragma unroll
            for (int r = 0; r < 4; r++) { int s = lane + (r<<5); if (s < S_) m = fmaxf(m, A->su4[warp][s]); }
#pragma unroll
            for (int off = 16; off > 0; off >>= 1) m = fmaxf(m, __shfl_xor_sync(0xffffffffu, m, off));
            float sum = 0.f;
#pragma unroll
            for (int r = 0; r < 4; r++) { int s = lane + (r<<5); if (s < S_) sum += expf(__fadd_rn(A->su4[warp][s], -m)); }
#pragma unroll
            for (int off = 16; off > 0; off >>= 1) sum += __shfl_xor_sync(0xffffffffu, sum, off);
            if (lane == 0) { A->red4[warp][0] = m; A->red4[warp][1] = sum; }
        }
        __syncthreads();
        if (warp < 4) {
#pragma unroll
            for (int r = 0; r < 4; r++) {
                int s = lane + (r << 5);
                if (s < S_)
                    A->ws4[warp][s] = __fdiv_rn(expf(__fadd_rn(A->su4[warp][s], -A->red4[warp][0])),
                                                A->red4[warp][1]);
            }
        }
        __syncthreads();
        {
            float acc[4] = {0.f, 0.f, 0.f, 0.f};
            const int nu = A->nu4[bi];
            for (int j = 0; j < nu; j++) {
                int s = A->slist[bi][j];
                float w = A->ws4[bi][s];
                const float* krow = kgl + ((size_t)s*B_ + bmine)*H_;
#pragma unroll
                for (int r = 0; r < 4; r++)
                    acc[r] = fmaf(w, krow[lane64 + (r << 6)], acc[r]);
            }
            __syncthreads();
#pragma unroll
            for (int r = 0; r < 4; r++)
                A->hsI[lane64 + (r << 6)][bi] = acc[r];
        }
        if (tid < 112) {
#pragma unroll
            for (int i = 0; i < 4; i++) A->su4[i][tid] = -INFINITY;
        }
        __syncthreads();
        // ---- pointer ----
        qproj4(pWqT, pqb, A);
        __syncthreads();
        attn_logits_pair(kptr, bmine, pV, K2, A, bi, sub);
        __syncthreads();
        if (warp < 4) {
            const int b = b0 + warp;
            float best = -INFINITY; int bidx = S_; float mx = -INFINITY;
#pragma unroll
            for (int r = 0; r < 4; r++) {
                int s = lane + (r << 5);
                if (s < S_) {
                    float lv = A->su4[warp][s];
                    mx = fmaxf(mx, lv);
                    float z = __fadd_rn(lv, gumbel_at(kk0, kk1, (unsigned)(b*S_ + s)));
                    if (z > best) { best = z; bidx = s; }
                }
            }
#pragma unroll
            for (int off = 16; off > 0; off >>= 1) {
                float oz = __shfl_xor_sync(0xffffffffu, best, off);
                int   oi = __shfl_xor_sync(0xffffffffu, bidx, off);
                if (oz > best || (oz == best && oi < bidx)) { best = oz; bidx = oi; }
                mx = fmaxf(mx, __shfl_xor_sync(0xffffffffu, mx, off));
            }
            float se = 0.f;
#pragma unroll
            for (int r = 0; r < 4; r++) { int s = lane + (r<<5); if (s < S_) se += expf(__fadd_rn(A->su4[warp][s], -mx)); }
#pragma unroll
            for (int off = 16; off > 0; off >>= 1) se += __shfl_xor_sync(0xffffffffu, se, off);
            if (lane == 0) {
                A->chosen4[warp] = bidx;
                out[(size_t)b*S_ + t] = __fadd_rn(__fadd_rn(A->su4[warp][bidx], -mx), -logf(se));
                out[(size_t)BS_ + (size_t)b*S_ + t] = (float)bidx;
                mask[(size_t)b*S_ + bidx] = 1;
            }
        }
        __syncthreads();
        {
            int ch = A->chosen4[bi];
            const float* src = emb + ((size_t)ch*B_ + bmine)*E_;
            float* dst = decin + (size_t)bmine*E_;
#pragma unroll
            for (int r = 0; r < 4; r++)
                dst[lane64 + (r << 6)] = src[lane64 + (r << 6)];
        }
        __syncthreads();
    }
}

__global__ __launch_bounds__(256, 4)
void mega_kernel(const float* __restrict__ inp,
                 const float* __restrict__ embW, const float* __restrict__ embB,
                 const float* __restrict__ eWih, const float* __restrict__ eWhh,
                 const float* __restrict__ ebih, const float* __restrict__ ebhh,
                 const float* __restrict__ dWih, const float* __restrict__ dWhh,
                 const float* __restrict__ dbih, const float* __restrict__ dbhh,
                 const float* __restrict__ pWq,  const float* __restrict__ pbq,
                 const float* __restrict__ pWk,  const float* __restrict__ pbk,
                 const float* __restrict__ pV,
                 const float* __restrict__ gWq,  const float* __restrict__ gbq,
                 const float* __restrict__ gWk,  const float* __restrict__ gbk,
                 const float* __restrict__ gV,
                 const float* __restrict__ sos,
                 float* __restrict__ out) {
    __shared__ ShU sh;
    const int tid = threadIdx.x;
    const int gstride = gridDim.x * blockDim.x;
    const int gidx = blockIdx.x * blockDim.x + tid;

    for (int i = gidx; i < B_*H_; i += gstride) { g_hbuf[0][i] = 0.f; g_c[i] = 0.f; }
    for (int i = gidx; i < B_*E_; i += gstride) g_decin[i] = sos[i & (E_-1)];
    for (int i = gidx; i < B_*S_; i += gstride) g_mask[i] = 0;
    for (int idx = gidx; idx < G4_*E_; idx += gstride) {
        int row = idx >> 8, kk = idx & 255;
        int j = row >> 2, g = row & 3;
        int old = (g*H_ + j)*E_ + kk;
        g_eWih_p[idx] = eWih[old];
        g_eWhh_p[idx] = eWhh[old];
        g_dWih_p[idx] = dWih[old];
        g_dWhh_p[idx] = dWhh[old];
    }
    for (int idx = gidx; idx < H_*H_; idx += gstride) {
        int kk = idx >> 8, n = idx & 255;
        g_gWqT[idx] = gWq[n*H_ + kk];
        g_pWqT[idx] = pWq[n*H_ + kk];
    }
    for (int idx = gidx; idx < G4_; idx += gstride) {
        int j = idx >> 2, g = idx & 3;
        int old = g*H_ + j;
        g_ebih_p[idx] = ebih[old];
        g_ebhh_p[idx] = ebhh[old];
        g_dbih_p[idx] = dbih[old];
        g_dbhh_p[idx] = dbhh[old];
    }
    if (blockIdx.x == 0 && tid < S_) {
        unsigned x0 = 0u, x1 = (unsigned)tid;
        threefry(0u, 42u, x0, x1);
        g_keys[2*tid]   = x0;
        g_keys[2*tid+1] = x1;
    }
    for (int idx = gidx; idx < S_*B_*E_; idx += gstride) {
        int e = idx & (E_-1);
        int i = idx >> 8;
        int s = i >> 11;
        int b = i & (B_-1);
        float x0 = inp[((size_t)b*S_ + s)*POS_ + 0];
        float x1 = inp[((size_t)b*S_ + s)*POS_ + 1];
        float dotv = fmaf(x1, embW[e*POS_ + 1], __fmul_rn(x0, embW[e*POS_ + 0]));
        g_emb[idx] = __fadd_rn(dotv, embB[e]);
    }
    gsync();

    dev_gemm_f<0>(g_emb, g_eWih_p, E_, nullptr, nullptr, 0, g_encgx, BS_, G4_,
                  g_ebih_p, nullptr, nullptr, nullptr, nullptr, nullptr, nullptr, sh.gemm);
    gsync();

    for (int t = 0; t < S_; t++) {
        dev_gemm_f<1>(g_hbuf[t & 1], g_eWhh_p, H_, nullptr, nullptr, 0,
                      nullptr, B_, G4_, nullptr,
                      g_encgx + (size_t)t*B_*G4_, nullptr, g_ebhh_p,
                      g_c, g_hbuf[(t + 1) & 1], g_encout + (size_t)t*B_*H_, sh.gemm);
        gsync();
    }

    dev_gemm_f<0>(g_encout, pWk, H_, nullptr, nullptr, 0, g_kptr, BS_, H_,
                  pbk, nullptr, nullptr, nullptr, nullptr, nullptr, nullptr, sh.gemm);
    dev_gemm_f<0>(g_encout, gWk, H_, nullptr, nullptr, 0, g_kgl, BS_, H_,
                  gbk, nullptr, nullptr, nullptr, nullptr, nullptr, nullptr, sh.gemm);
    gsync();

    for (int t = 0; t < S_; t++) {
        dev_gemm_f<2>(g_decin, g_dWih_p, E_, g_hbuf[t & 1], g_dWhh_p, H_,
                      nullptr, B_, G4_, nullptr,
                      nullptr, g_dbih_p, g_dbhh_p,
                      g_c, g_hbuf[(t + 1) & 1], nullptr, sh.gemm);
        gsync();
        dev_dec_tail(g_hbuf[(t + 1) & 1],
                     g_gWqT, gbq, g_kgl, gV,
                     g_pWqT, pbq, g_kptr, pV,
                     g_mask, g_keys, g_emb, g_decin, out, t, &sh.attn);
        gsync();
    }
}

extern "C" void kernel_launch(void* const* d_in, const int* in_sizes, int n_in,
                              void* d_out, int out_size) {
    const float* inp  = (const float*)d_in[0];
    const float* embW = (const float*)d_in[1];
    const float* embB = (const float*)d_in[2];
    const float* eWih = (const float*)d_in[3];
    const float* eWhh = (const float*)d_in[4];
    const float* ebih = (const float*)d_in[5];
    const float* ebhh = (const float*)d_in[6];
    const float* dWih = (const float*)d_in[7];
    const float* dWhh = (const float*)d_in[8];
    const float* dbih = (const float*)d_in[9];
    const float* dbhh = (const float*)d_in[10];
    const float* pWq  = (const float*)d_in[11];
    const float* pbq  = (const float*)d_in[12];
    const float* pWk  = (const float*)d_in[13];
    const float* pbk  = (const float*)d_in[14];
    const float* pV   = (const float*)d_in[15];
    const float* gWq  = (const float*)d_in[16];
    const float* gbq  = (const float*)d_in[17];
    const float* gWk  = (const float*)d_in[18];
    const float* gbk  = (const float*)d_in[19];
    const float* gV   = (const float*)d_in[20];
    const float* sos  = (const float*)d_in[21];
    float* out = (float*)d_out;

    int sms = 0;
    cudaDeviceGetAttribute(&sms, cudaDevAttrMultiProcessorCount, 0);
    int nblk = sms * 4;

    mega_kernel<<<nblk, 256>>>(
        inp, embW, embB, eWih, eWhh, ebih, ebhh,
        dWih, dWhh, dbih, dbhh,
        pWq, pbq, pWk, pbk, pV,
        gWq, gbq, gWk, gbk, gV, sos, out);
}